// round 8
// baseline (speedup 1.0000x reference)
#include <cuda_runtime.h>
#include <cuda_bf16.h>
#include <math.h>
#include <stdint.h>

#define BB   4
#define TLEN 32768
#define NM   80
#define RC   120
#define SC   240
#define NBLK 16
#define NC   256

// ---------------- device scratch (no allocations allowed) ----------------
__device__ uint4 g_resAH[BB * TLEN * 16];
__device__ uint4 g_resAL[BB * TLEN * 16];
__device__ uint4 g_resBH[BB * TLEN * 16];
__device__ uint4 g_resBL[BB * TLEN * 16];
__device__ uint4 g_condH[BB * TLEN * 16];
__device__ uint4 g_condL[BB * TLEN * 16];
__device__ float g_skip [BB * TLEN * SC];   // [b][t][c]
__device__ float g_skipT[BB * SC * TLEN];   // [b][c][t]
__device__ float g_o    [BB * NC * TLEN];
__device__ uint4 g_W1h[NBLK * 6 * 1920];    // phase1, rows = permuted n (240)
__device__ uint4 g_W1l[NBLK * 6 * 1920];
__device__ uint4 g_W2sh[NBLK * 2 * 1920];   // skip [240][64]
__device__ uint4 g_W2sl[NBLK * 2 * 1920];
__device__ uint4 g_W2rh[NBLK * 2 * 960];    // res  [120][64]
__device__ uint4 g_W2rl[NBLK * 2 * 960];
__device__ float g_Wo[240 * 256];           // out_w transposed [k][o]
__device__ float g_We[256 * 256];           // end_w transposed [k][o]

// ---------------- helpers -------------------------------------------------
__device__ __forceinline__ uint32_t smem_u32(const void* p) {
    uint32_t a;
    asm("{ .reg .u64 t; cvta.to.shared.u64 t, %1; cvt.u32.u64 %0, t; }"
        : "=r"(a) : "l"(p));
    return a;
}
__device__ __forceinline__ uint32_t sw128(uint32_t b) { return b ^ ((b >> 3) & 0x70); }

union U4B { uint4 u; __nv_bfloat16 h[8]; };
union U1B { uint32_t u; __nv_bfloat16 h[2]; };

__device__ __forceinline__ void split_bf16(float x, __nv_bfloat16& hi, __nv_bfloat16& lo) {
    hi = __float2bfloat16(x);
    lo = __float2bfloat16(x - __bfloat162float(hi));
}
__device__ __forceinline__ float fast_tanh(float x) {
    return 1.f - 2.f / (1.f + __expf(2.f * x));
}
__device__ __forceinline__ float fast_sigmoid(float x) {
    return 1.f / (1.f + __expf(-x));
}

__device__ __forceinline__ void ldsm_x4(uint32_t* r, uint32_t addr) {
    asm volatile("ldmatrix.sync.aligned.m8n8.x4.shared.b16 {%0,%1,%2,%3}, [%4];"
                 : "=r"(r[0]), "=r"(r[1]), "=r"(r[2]), "=r"(r[3]) : "r"(addr));
}
__device__ __forceinline__ void ldsm_x2(uint32_t* r, uint32_t addr) {
    asm volatile("ldmatrix.sync.aligned.m8n8.x2.shared.b16 {%0,%1}, [%2];"
                 : "=r"(r[0]), "=r"(r[1]) : "r"(addr));
}
__device__ __forceinline__ void mma16816(float* c, const uint32_t* a,
                                         uint32_t b0, uint32_t b1) {
    asm volatile("mma.sync.aligned.m16n8k16.row.col.f32.bf16.bf16.f32 "
                 "{%0,%1,%2,%3}, {%4,%5,%6,%7}, {%8,%9}, {%0,%1,%2,%3};"
                 : "+f"(c[0]), "+f"(c[1]), "+f"(c[2]), "+f"(c[3])
                 : "r"(a[0]), "r"(a[1]), "r"(a[2]), "r"(a[3]), "r"(b0), "r"(b1));
}

// ---------------- weight repack kernels -----------------------------------
__global__ void repack_w1(const float* __restrict__ dil_w,
                          const float* __restrict__ cond_w) {
    int idx = blockIdx.x * blockDim.x + threadIdx.x;
    const int total = NBLK * 6 * 240 * 64;
    if (idx >= total) return;
    int kk = idx & 63;
    int n  = (idx >> 6) % 240;
    int q  = (idx / (64 * 240)) % 6;
    int i  = idx / (64 * 240 * 6);
    int c  = (n >> 1) + (n & 1) * 120;          // original output channel
    int kc = (q & 1) * 64 + kk;
    float w = 0.f;
    if (q < 2)      { if (kc < 120) w = dil_w[((i*240 + c)*120 + kc)*2 + 0]; }
    else if (q < 4) { if (kc < 120) w = dil_w[((i*240 + c)*120 + kc)*2 + 1]; }
    else            { if (kc < 80)  w = cond_w[(i*240 + c)*80 + kc]; }
    __nv_bfloat16 hi, lo; split_bf16(w, hi, lo);
    int elem = sw128(n * 128 + kk * 2) >> 1;
    size_t base = (size_t)(i * 6 + q) * 15360;
    ((__nv_bfloat16*)g_W1h)[base + elem] = hi;
    ((__nv_bfloat16*)g_W1l)[base + elem] = lo;
}

__global__ void repack_w2(const float* __restrict__ skip_w,
                          const float* __restrict__ res_w) {
    int idx = blockIdx.x * blockDim.x + threadIdx.x;
    const int totS = NBLK * 2 * 240 * 64;
    const int totR = NBLK * 2 * 120 * 64;
    if (idx < totS) {
        int kk = idx & 63;
        int c  = (idx >> 6) % 240;
        int q  = (idx / (64 * 240)) % 2;
        int i  = idx / (64 * 240 * 2);
        int k  = q * 64 + kk;
        float w = (k < 120) ? skip_w[(i*240 + c)*120 + k] : 0.f;
        __nv_bfloat16 hi, lo; split_bf16(w, hi, lo);
        int elem = sw128(c * 128 + kk * 2) >> 1;
        size_t base = (size_t)(i * 2 + q) * 15360;
        ((__nv_bfloat16*)g_W2sh)[base + elem] = hi;
        ((__nv_bfloat16*)g_W2sl)[base + elem] = lo;
    } else if (idx < totS + totR) {
        int j = idx - totS;
        int kk = j & 63;
        int c  = (j >> 6) % 120;
        int q  = (j / (64 * 120)) % 2;
        int i  = j / (64 * 120 * 2);
        int k  = q * 64 + kk;
        float w = (k < 120) ? res_w[(i*120 + c)*120 + k] : 0.f;
        __nv_bfloat16 hi, lo; split_bf16(w, hi, lo);
        int elem = sw128(c * 128 + kk * 2) >> 1;
        size_t base = (size_t)(i * 2 + q) * 7680;
        ((__nv_bfloat16*)g_W2rh)[base + elem] = hi;
        ((__nv_bfloat16*)g_W2rl)[base + elem] = lo;
    }
}

__global__ void repack_wf(const float* __restrict__ out_w,
                          const float* __restrict__ end_w) {
    int idx = blockIdx.x * blockDim.x + threadIdx.x;
    if (idx < 240 * 256) {
        int k = idx / 256, o = idx % 256;
        g_Wo[idx] = out_w[o * 240 + k];
    } else if (idx < 240 * 256 + 256 * 256) {
        int j = idx - 240 * 256;
        int k = j / 256, o = j % 256;
        g_We[j] = end_w[o * 256 + k];
    }
}

// ---------------- prologues -----------------------------------------------
__global__ void prologue_res(const float* __restrict__ wav,
                             const float* __restrict__ wav_w,
                             const float* __restrict__ wav_b) {
    int idx = blockIdx.x * blockDim.x + threadIdx.x;
    const int total = BB * TLEN * 16;
    if (idx >= total) return;
    int chunk = idx & 15;
    int t = (idx >> 4) % TLEN;
    int b = idx / (TLEN * 16);
    float wv = wav[(size_t)b * TLEN + t];
    U4B uh, ul;
    #pragma unroll
    for (int e = 0; e < 8; e++) {
        int c = chunk * 8 + e;
        float v = (c < RC) ? (wav_w[c] * wv + wav_b[c]) : 0.f;
        split_bf16(v, uh.h[e], ul.h[e]);
    }
    g_resAH[idx] = uh.u;
    g_resAL[idx] = ul.u;
}

__global__ void prologue_cond(const float* __restrict__ cond) {
    int idx = blockIdx.x * blockDim.x + threadIdx.x;
    const int total = BB * TLEN * 16;
    if (idx >= total) return;
    int chunk = idx & 15;
    int t = (idx >> 4) % TLEN;
    int b = idx / (TLEN * 16);
    U4B uh, ul;
    #pragma unroll
    for (int e = 0; e < 8; e++) {
        int c = chunk * 8 + e;
        float v = (c < NM) ? cond[((size_t)b * NM + c) * TLEN + t] : 0.f;
        split_bf16(v, uh.h[e], ul.h[e]);
    }
    g_condH[idx] = uh.u;
    g_condL[idx] = ul.u;
}

// ---------------- mma per-layer kernel (512 threads, 16 warps) ------------
#define OFF_BA   0        // 240 floats
#define OFF_BB   1024     // 360 floats
#define OFF_XH   4096     // [128][64] bf16 = 16384
#define OFF_XL   20480
#define OFF_WH   36864    // [240][64] bf16 = 30720
#define OFF_WL   67584
#define OFF_RH   98304    // [2][120][64] bf16 = 30720
#define OFF_RL   129024
#define OFF_A2H  159744   // [2][128][64] bf16 = 32768
#define OFF_A2L  192512
#define SMEM_MMA 225280

__global__ void __launch_bounds__(512, 1) block_mma(
    const float* __restrict__ dil_b, const float* __restrict__ cond_b,
    const float* __restrict__ skip_b, const float* __restrict__ res_b,
    int layer, int d, int first, int swap)
{
    extern __shared__ __align__(16) char sm[];
    const uint32_t smb = smem_u32(sm);
    const int tid  = threadIdx.x;
    const int lane = tid & 31;
    const int wid  = tid >> 5;
    const int mw   = wid >> 1;            // 0..7 (m, 16 rows each)
    const int nw   = wid & 1;             // 0..1 (n)
    const int b    = blockIdx.y;
    const int t0   = blockIdx.x * 128;

    const uint4* resInH = swap ? g_resBH : g_resAH;
    const uint4* resInL = swap ? g_resBL : g_resAL;
    uint4* resOutH = swap ? g_resAH : g_resBH;
    uint4* resOutL = swap ? g_resAL : g_resBL;

    float* biasA = (float*)(sm + OFF_BA);
    float* biasB = (float*)(sm + OFF_BB);
    for (int e = tid; e < 240; e += 512)
        biasA[e] = dil_b[layer * 240 + e] + cond_b[layer * 240 + e];
    for (int e = tid; e < 360; e += 512)
        biasB[e] = (e < 240) ? skip_b[layer * 240 + e] : res_b[layer * 120 + e - 240];
    // zero-pad phase2 A region B: k 56..63 (p 120..127)
    if (tid < 128) {
        uint32_t byte = tid * 128 + ((7u ^ (tid & 7)) << 4);
        *(uint4*)(sm + OFF_A2H + 16384 + byte) = make_uint4(0, 0, 0, 0);
        *(uint4*)(sm + OFF_A2L + 16384 + byte) = make_uint4(0, 0, 0, 0);
    }

    // ========== phase 1: g[128t x 240n(permuted)], K=384 ==========
    float ac[15][4];
    #pragma unroll
    for (int nt = 0; nt < 15; nt++)
        #pragma unroll
        for (int e = 0; e < 4; e++) ac[nt][e] = 0.f;

    for (int q = 0; q < 6; q++) {
        __syncthreads();
        {   // stage X chunk [128][64] hi/lo
            const uint4* srcH; const uint4* srcL; int tshift, half;
            if (q < 2)      { srcH = resInH; srcL = resInL; tshift = t0 - d; half = q; }
            else if (q < 4) { srcH = resInH; srcL = resInL; tshift = t0;     half = q - 2; }
            else            { srcH = g_condH; srcL = g_condL; tshift = t0;   half = q - 4; }
            for (int e = tid; e < 1024; e += 512) {
                int r = e >> 3, ii = e & 7;
                int t = tshift + r;
                uint4 vh = make_uint4(0,0,0,0), vl = make_uint4(0,0,0,0);
                if (t >= 0) {
                    size_t si = ((size_t)b * TLEN + t) * 16 + half * 8 + ii;
                    vh = srcH[si]; vl = srcL[si];
                }
                uint32_t byte = sw128((r << 7) + (ii << 4));
                *(uint4*)(sm + OFF_XH + byte) = vh;
                *(uint4*)(sm + OFF_XL + byte) = vl;
            }
            size_t wb = (size_t)(layer * 6 + q) * 1920;
            for (int e = tid; e < 1920; e += 512) {
                ((uint4*)(sm + OFF_WH))[e] = g_W1h[wb + e];
                ((uint4*)(sm + OFF_WL))[e] = g_W1l[wb + e];
            }
        }
        __syncthreads();
        #pragma unroll
        for (int kt = 0; kt < 4; kt++) {
            uint32_t ah[4], al[4];
            {
                int ar = mw * 16 + (lane & 15);
                int ack = kt * 2 + (lane >> 4);
                uint32_t ab = ar * 128 + (((uint32_t)(ack ^ (ar & 7))) << 4);
                ldsm_x4(ah, smb + OFF_XH + ab);
                ldsm_x4(al, smb + OFF_XL + ab);
            }
            int bn = nw * 120 + (lane & 7);
            int bsel = (lane >> 3) & 1;
            #pragma unroll
            for (int nt = 0; nt < 15; nt++) {
                int n = bn + nt * 8;
                int bck = kt * 2 + bsel;
                uint32_t bb = n * 128 + (((uint32_t)(bck ^ (n & 7))) << 4);
                uint32_t bh[2], bl[2];
                ldsm_x2(bh, smb + OFF_WH + bb);
                ldsm_x2(bl, smb + OFF_WL + bb);
                mma16816(ac[nt], ah, bh[0], bh[1]);
                mma16816(ac[nt], ah, bl[0], bl[1]);
                mma16816(ac[nt], al, bh[0], bh[1]);
            }
        }
    }

    // ========== gating (in registers) -> phase2 A tile ==========
    #pragma unroll
    for (int nt = 0; nt < 15; nt++) {
        int p = nw * 60 + nt * 4 + (lane & 3);
        int reg = (p < 64) ? 0 : 1;
        int p2 = p & 63;
        float ba_t = biasA[p];
        float ba_s = biasA[p + 120];
        #pragma unroll
        for (int rh = 0; rh < 2; rh++) {
            int r = mw * 16 + (lane >> 2) + rh * 8;
            float gt = ac[nt][rh * 2 + 0] + ba_t;
            float gs = ac[nt][rh * 2 + 1] + ba_s;
            float v = fast_tanh(gt) * fast_sigmoid(gs);
            __nv_bfloat16 hi, lo; split_bf16(v, hi, lo);
            uint32_t byte = r * 128 + (((uint32_t)((p2 >> 3) ^ (r & 7))) << 4)
                          + (p2 & 7) * 2;
            *(__nv_bfloat16*)(sm + OFF_A2H + reg * 16384 + byte) = hi;
            *(__nv_bfloat16*)(sm + OFF_A2L + reg * 16384 + byte) = lo;
        }
    }

    // ========== phase 2a: skip[128t x 240c], K=120 ==========
    float sk[15][4];
    #pragma unroll
    for (int nt = 0; nt < 15; nt++)
        #pragma unroll
        for (int e = 0; e < 4; e++) sk[nt][e] = 0.f;

    for (int q2 = 0; q2 < 2; q2++) {
        __syncthreads();
        {
            size_t bs = (size_t)(layer * 2 + q2) * 1920;
            size_t br = (size_t)(layer * 2 + q2) * 960;
            for (int e = tid; e < 1920; e += 512) {
                ((uint4*)(sm + OFF_WH))[e] = g_W2sh[bs + e];
                ((uint4*)(sm + OFF_WL))[e] = g_W2sl[bs + e];
            }
            for (int e = tid; e < 960; e += 512) {
                ((uint4*)(sm + OFF_RH + q2 * 15360))[e] = g_W2rh[br + e];
                ((uint4*)(sm + OFF_RL + q2 * 15360))[e] = g_W2rl[br + e];
            }
        }
        __syncthreads();
        #pragma unroll
        for (int kt = 0; kt < 4; kt++) {
            uint32_t ah[4], al[4];
            {
                int ar = mw * 16 + (lane & 15);
                int ack = kt * 2 + (lane >> 4);
                uint32_t ab = ar * 128 + (((uint32_t)(ack ^ (ar & 7))) << 4);
                ldsm_x4(ah, smb + OFF_A2H + q2 * 16384 + ab);
                ldsm_x4(al, smb + OFF_A2L + q2 * 16384 + ab);
            }
            int bn = nw * 120 + (lane & 7);
            int bsel = (lane >> 3) & 1;
            #pragma unroll
            for (int nt = 0; nt < 15; nt++) {
                int n = bn + nt * 8;
                int bck = kt * 2 + bsel;
                uint32_t bb = n * 128 + (((uint32_t)(bck ^ (n & 7))) << 4);
                uint32_t bh[2], bl[2];
                ldsm_x2(bh, smb + OFF_WH + bb);
                ldsm_x2(bl, smb + OFF_WL + bb);
                mma16816(sk[nt], ah, bh[0], bh[1]);
                mma16816(sk[nt], ah, bl[0], bl[1]);
                mma16816(sk[nt], al, bh[0], bh[1]);
            }
        }
    }

    // skip epilogue: [b][t][240] fp32 accumulate
    #pragma unroll
    for (int nt = 0; nt < 15; nt++) {
        int c = nw * 120 + nt * 8 + 2 * (lane & 3);
        float b0 = biasB[c], b1 = biasB[c + 1];
        #pragma unroll
        for (int rh = 0; rh < 2; rh++) {
            int t = t0 + mw * 16 + (lane >> 2) + rh * 8;
            size_t gi = ((size_t)b * TLEN + t) * 240 + c;
            float2 v;
            v.x = sk[nt][rh * 2 + 0] + b0;
            v.y = sk[nt][rh * 2 + 1] + b1;
            if (!first) {
                float2 o = *(float2*)(g_skip + gi);
                v.x += o.x; v.y += o.y;
            }
            *(float2*)(g_skip + gi) = v;
        }
    }

    // ========== phase 2b: res[128t x 120c], K=120 ==========
    {
        float rs[8][4];
        #pragma unroll
        for (int nt = 0; nt < 8; nt++)
            #pragma unroll
            for (int e = 0; e < 4; e++) rs[nt][e] = 0.f;
        const int NT = 8 - nw;

        for (int q2 = 0; q2 < 2; q2++) {
            #pragma unroll
            for (int kt = 0; kt < 4; kt++) {
                uint32_t ah[4], al[4];
                {
                    int ar = mw * 16 + (lane & 15);
                    int ack = kt * 2 + (lane >> 4);
                    uint32_t ab = ar * 128 + (((uint32_t)(ack ^ (ar & 7))) << 4);
                    ldsm_x4(ah, smb + OFF_A2H + q2 * 16384 + ab);
                    ldsm_x4(al, smb + OFF_A2L + q2 * 16384 + ab);
                }
                int bn = nw * 64 + (lane & 7);
                int bsel = (lane >> 3) & 1;
                #pragma unroll
                for (int nt = 0; nt < 8; nt++) {
                    if (nt < NT) {
                        int n = bn + nt * 8;
                        int bck = kt * 2 + bsel;
                        uint32_t bb = n * 128 + (((uint32_t)(bck ^ (n & 7))) << 4);
                        uint32_t bh[2], bl[2];
                        ldsm_x2(bh, smb + OFF_RH + q2 * 15360 + bb);
                        ldsm_x2(bl, smb + OFF_RL + q2 * 15360 + bb);
                        mma16816(rs[nt], ah, bh[0], bh[1]);
                        mma16816(rs[nt], ah, bl[0], bl[1]);
                        mma16816(rs[nt], al, bh[0], bh[1]);
                    }
                }
            }
        }

        // res epilogue
        const uint32_t* rInH = (const uint32_t*)resInH;
        const uint32_t* rInL = (const uint32_t*)resInL;
        uint32_t* rOutH = (uint32_t*)resOutH;
        uint32_t* rOutL = (uint32_t*)resOutL;
        #pragma unroll
        for (int nt = 0; nt < 8; nt++) {
            if (nt < NT) {
                int c = nw * 64 + nt * 8 + 2 * (lane & 3);
                float b0 = biasB[240 + c], b1 = biasB[240 + c + 1];
                #pragma unroll
                for (int rh = 0; rh < 2; rh++) {
                    int t = t0 + mw * 16 + (lane >> 2) + rh * 8;
                    size_t ri = ((size_t)b * TLEN + t) * 64 + (c >> 1);
                    U1B vh, vl, oh, ol;
                    vh.u = rInH[ri]; vl.u = rInL[ri];
                    float o0 = rs[nt][rh * 2 + 0] + b0
                             + __bfloat162float(vh.h[0]) + __bfloat162float(vl.h[0]);
                    float o1 = rs[nt][rh * 2 + 1] + b1
                             + __bfloat162float(vh.h[1]) + __bfloat162float(vl.h[1]);
                    split_bf16(o0, oh.h[0], ol.h[0]);
                    split_bf16(o1, oh.h[1], ol.h[1]);
                    rOutH[ri] = oh.u;
                    rOutL[ri] = ol.u;
                }
            }
        }
    }
    // zero pad channels 120-127 of resOut
    if (tid < 128) {
        size_t rp = ((size_t)b * TLEN + t0 + tid) * 16 + 15;
        resOutH[rp] = make_uint4(0, 0, 0, 0);
        resOutL[rp] = make_uint4(0, 0, 0, 0);
    }
}

// ---------------- skip transpose [b][t][c] -> [b][c][t] -------------------
__global__ void transpose_skip() {
    __shared__ float tile[32][33];
    int b  = blockIdx.z;
    int c0 = blockIdx.y * 32;
    int t0 = blockIdx.x * 32;
    int tx = threadIdx.x, ty = threadIdx.y;   // (32, 8)
    #pragma unroll
    for (int k = 0; k < 4; k++) {
        int c = c0 + tx, t = t0 + ty + k * 8;
        tile[ty + k * 8][tx] = (c < SC) ? g_skip[((size_t)b * TLEN + t) * SC + c] : 0.f;
    }
    __syncthreads();
    #pragma unroll
    for (int k = 0; k < 4; k++) {
        int c = c0 + ty + k * 8, t = t0 + tx;
        if (c < SC) g_skipT[((size_t)b * SC + c) * TLEN + t] = tile[tx][ty + k * 8];
    }
}

// ---------------- fp32 head kernels ---------------------------------------
__global__ void __launch_bounds__(256, 2) final1_kernel(
    const float* __restrict__ out_b)
{
    __shared__ float Ws[8 * 256];
    __shared__ float Bs[8 * 64];
    const int tid = threadIdx.x;
    const int tx = tid & 15, ty = tid >> 4;
    const int t0 = blockIdx.x * 64;
    const int b  = blockIdx.y;

    float acc[16][4];
    #pragma unroll
    for (int j = 0; j < 16; j++) {
        float bv = out_b[ty + 16 * j];
        #pragma unroll
        for (int m = 0; m < 4; m++) acc[j][m] = bv;
    }
    for (int kc = 0; kc < 30; kc++) {
        int kb = kc * 8;
        __syncthreads();
        for (int e = tid; e < 8 * 64; e += 256) {
            int kk = e >> 6, tt = e & 63;
            float v = g_skipT[((size_t)b * SC + kb + kk) * TLEN + t0 + tt];
            Bs[e] = fmaxf(v, 0.f);
        }
        for (int e = tid; e < 8 * 256; e += 256) Ws[e] = g_Wo[kb * 256 + e];
        __syncthreads();
        #pragma unroll
        for (int kk = 0; kk < 8; kk++) {
            float a0 = Bs[kk * 64 + tx];
            float a1 = Bs[kk * 64 + tx + 16];
            float a2 = Bs[kk * 64 + tx + 32];
            float a3 = Bs[kk * 64 + tx + 48];
            const float* wr = &Ws[kk * 256 + ty];
            #pragma unroll
            for (int j = 0; j < 16; j++) {
                float w = wr[16 * j];
                acc[j][0] += w * a0; acc[j][1] += w * a1;
                acc[j][2] += w * a2; acc[j][3] += w * a3;
            }
        }
    }
    #pragma unroll
    for (int j = 0; j < 16; j++) {
        int o = ty + 16 * j;
        #pragma unroll
        for (int m = 0; m < 4; m++)
            g_o[((size_t)b * NC + o) * TLEN + t0 + tx + 16 * m] = acc[j][m];
    }
}

__global__ void __launch_bounds__(256, 2) final2_kernel(
    const float* __restrict__ end_b, float* __restrict__ out)
{
    __shared__ float Ws[8 * 256];
    __shared__ float Bs[8 * 64];
    const int tid = threadIdx.x;
    const int tx = tid & 15, ty = tid >> 4;
    const int t0 = blockIdx.x * 64;
    const int b  = blockIdx.y;

    float acc[16][4];
    #pragma unroll
    for (int j = 0; j < 16; j++) {
        float bv = end_b[ty + 16 * j];
        #pragma unroll
        for (int m = 0; m < 4; m++) acc[j][m] = bv;
    }
    for (int kc = 0; kc < 32; kc++) {
        int kb = kc * 8;
        __syncthreads();
        for (int e = tid; e < 8 * 64; e += 256) {
            int kk = e >> 6, tt = e & 63;
            float v = g_o[((size_t)b * NC + kb + kk) * TLEN + t0 + tt];
            Bs[e] = fmaxf(v, 0.f);
        }
        for (int e = tid; e < 8 * 256; e += 256) Ws[e] = g_We[kb * 256 + e];
        __syncthreads();
        #pragma unroll
        for (int kk = 0; kk < 8; kk++) {
            float a0 = Bs[kk * 64 + tx];
            float a1 = Bs[kk * 64 + tx + 16];
            float a2 = Bs[kk * 64 + tx + 32];
            float a3 = Bs[kk * 64 + tx + 48];
            const float* wr = &Ws[kk * 256 + ty];
            #pragma unroll
            for (int j = 0; j < 16; j++) {
                float w = wr[16 * j];
                acc[j][0] += w * a0; acc[j][1] += w * a1;
                acc[j][2] += w * a2; acc[j][3] += w * a3;
            }
        }
    }
    #pragma unroll
    for (int j = 0; j < 16; j++) {
        int o = ty + 16 * j;
        #pragma unroll
        for (int m = 0; m < 4; m++)
            out[((size_t)b * NC + o) * TLEN + t0 + tx + 16 * m] = acc[j][m];
    }
}

// ---------------- host launcher -------------------------------------------
extern "C" void kernel_launch(void* const* d_in, const int* in_sizes, int n_in,
                              void* d_out, int out_size) {
    const float* wav    = (const float*)d_in[0];
    const float* cond   = (const float*)d_in[1];
    const float* wav_w  = (const float*)d_in[2];
    const float* wav_b  = (const float*)d_in[3];
    const float* cond_w = (const float*)d_in[4];
    const float* cond_b = (const float*)d_in[5];
    const float* dil_w  = (const float*)d_in[6];
    const float* dil_b  = (const float*)d_in[7];
    const float* skip_w = (const float*)d_in[8];
    const float* skip_b = (const float*)d_in[9];
    const float* res_w  = (const float*)d_in[10];
    const float* res_b  = (const float*)d_in[11];
    const float* out_w  = (const float*)d_in[12];
    const float* out_b  = (const float*)d_in[13];
    const float* end_w  = (const float*)d_in[14];
    const float* end_b  = (const float*)d_in[15];

    cudaFuncSetAttribute(block_mma, cudaFuncAttributeMaxDynamicSharedMemorySize,
                         SMEM_MMA);

    repack_w1<<<(NBLK * 6 * 240 * 64 + 255) / 256, 256>>>(dil_w, cond_w);
    repack_w2<<<(NBLK * 2 * (240 + 120) * 64 + 255) / 256, 256>>>(skip_w, res_w);
    repack_wf<<<(240 * 256 + 256 * 256 + 255) / 256, 256>>>(out_w, end_w);
    prologue_res<<<(BB * TLEN * 16 + 255) / 256, 256>>>(wav, wav_w, wav_b);
    prologue_cond<<<(BB * TLEN * 16 + 255) / 256, 256>>>(cond);

    dim3 gridB(TLEN / 128, BB);
    for (int i = 0; i < NBLK; i++) {
        int d = 1 << (i % 8);
        block_mma<<<gridB, 512, SMEM_MMA>>>(dil_b, cond_b, skip_b, res_b,
                                            i, d, (i == 0) ? 1 : 0, i & 1);
    }
    dim3 gridT(TLEN / 32, 8, BB);
    transpose_skip<<<gridT, dim3(32, 8)>>>();
    dim3 gridH(TLEN / 64, BB);
    final1_kernel<<<gridH, 256>>>(out_b);
    final2_kernel<<<gridH, 256>>>(end_b, (float*)d_out);
}

// round 9
// speedup vs baseline: 1.2767x; 1.2767x over previous
#include <cuda_runtime.h>
#include <cuda_bf16.h>
#include <math.h>
#include <stdint.h>

#define BB   4
#define TLEN 32768
#define NM   80
#define RC   120
#define SC   240
#define NBLK 16
#define NC   256

// ---------------- device scratch (no allocations allowed) ----------------
__device__ uint4 g_resAH[BB * TLEN * 16];
__device__ uint4 g_resAL[BB * TLEN * 16];
__device__ uint4 g_resBH[BB * TLEN * 16];
__device__ uint4 g_resBL[BB * TLEN * 16];
__device__ uint4 g_condH[BB * TLEN * 16];
__device__ uint4 g_condL[BB * TLEN * 16];
__device__ float g_skip [BB * TLEN * SC];   // [b][t][c]
__device__ uint4 g_W1h[NBLK * 6 * 1920];    // phase1, rows = permuted n (240)
__device__ uint4 g_W1l[NBLK * 6 * 1920];
__device__ uint4 g_W2sh[NBLK * 2 * 1920];   // skip [240][64]
__device__ uint4 g_W2sl[NBLK * 2 * 1920];
__device__ uint4 g_W2rh[NBLK * 2 * 960];    // res  [120][64]
__device__ uint4 g_W2rl[NBLK * 2 * 960];
__device__ uint4 g_Woh[4 * 2048];           // out_w [256][64] chunks, swizzled
__device__ uint4 g_Wol[4 * 2048];
__device__ uint4 g_Weh[4 * 2048];           // end_w [256][64] chunks, swizzled
__device__ uint4 g_Wel[4 * 2048];

// ---------------- helpers -------------------------------------------------
__device__ __forceinline__ uint32_t smem_u32(const void* p) {
    uint32_t a;
    asm("{ .reg .u64 t; cvta.to.shared.u64 t, %1; cvt.u32.u64 %0, t; }"
        : "=r"(a) : "l"(p));
    return a;
}
__device__ __forceinline__ uint32_t sw128(uint32_t b) { return b ^ ((b >> 3) & 0x70); }

union U4B { uint4 u; __nv_bfloat16 h[8]; };
union U1B { uint32_t u; __nv_bfloat16 h[2]; };

__device__ __forceinline__ void split_bf16(float x, __nv_bfloat16& hi, __nv_bfloat16& lo) {
    hi = __float2bfloat16(x);
    lo = __float2bfloat16(x - __bfloat162float(hi));
}
__device__ __forceinline__ float fast_tanh(float x) {
    return 1.f - 2.f / (1.f + __expf(2.f * x));
}
__device__ __forceinline__ float fast_sigmoid(float x) {
    return 1.f / (1.f + __expf(-x));
}

__device__ __forceinline__ void ldsm_x4(uint32_t* r, uint32_t addr) {
    asm volatile("ldmatrix.sync.aligned.m8n8.x4.shared.b16 {%0,%1,%2,%3}, [%4];"
                 : "=r"(r[0]), "=r"(r[1]), "=r"(r[2]), "=r"(r[3]) : "r"(addr));
}
__device__ __forceinline__ void ldsm_x2(uint32_t* r, uint32_t addr) {
    asm volatile("ldmatrix.sync.aligned.m8n8.x2.shared.b16 {%0,%1}, [%2];"
                 : "=r"(r[0]), "=r"(r[1]) : "r"(addr));
}
__device__ __forceinline__ void mma16816(float* c, const uint32_t* a,
                                         uint32_t b0, uint32_t b1) {
    asm volatile("mma.sync.aligned.m16n8k16.row.col.f32.bf16.bf16.f32 "
                 "{%0,%1,%2,%3}, {%4,%5,%6,%7}, {%8,%9}, {%0,%1,%2,%3};"
                 : "+f"(c[0]), "+f"(c[1]), "+f"(c[2]), "+f"(c[3])
                 : "r"(a[0]), "r"(a[1]), "r"(a[2]), "r"(a[3]), "r"(b0), "r"(b1));
}

// ---------------- weight repack kernels -----------------------------------
__global__ void repack_w1(const float* __restrict__ dil_w,
                          const float* __restrict__ cond_w) {
    int idx = blockIdx.x * blockDim.x + threadIdx.x;
    const int total = NBLK * 6 * 240 * 64;
    if (idx >= total) return;
    int kk = idx & 63;
    int n  = (idx >> 6) % 240;
    int q  = (idx / (64 * 240)) % 6;
    int i  = idx / (64 * 240 * 6);
    int c  = (n >> 1) + (n & 1) * 120;          // original output channel
    int kc = (q & 1) * 64 + kk;
    float w = 0.f;
    if (q < 2)      { if (kc < 120) w = dil_w[((i*240 + c)*120 + kc)*2 + 0]; }
    else if (q < 4) { if (kc < 120) w = dil_w[((i*240 + c)*120 + kc)*2 + 1]; }
    else            { if (kc < 80)  w = cond_w[(i*240 + c)*80 + kc]; }
    __nv_bfloat16 hi, lo; split_bf16(w, hi, lo);
    int elem = sw128(n * 128 + kk * 2) >> 1;
    size_t base = (size_t)(i * 6 + q) * 15360;
    ((__nv_bfloat16*)g_W1h)[base + elem] = hi;
    ((__nv_bfloat16*)g_W1l)[base + elem] = lo;
}

__global__ void repack_w2(const float* __restrict__ skip_w,
                          const float* __restrict__ res_w) {
    int idx = blockIdx.x * blockDim.x + threadIdx.x;
    const int totS = NBLK * 2 * 240 * 64;
    const int totR = NBLK * 2 * 120 * 64;
    if (idx < totS) {
        int kk = idx & 63;
        int c  = (idx >> 6) % 240;
        int q  = (idx / (64 * 240)) % 2;
        int i  = idx / (64 * 240 * 2);
        int k  = q * 64 + kk;
        float w = (k < 120) ? skip_w[(i*240 + c)*120 + k] : 0.f;
        __nv_bfloat16 hi, lo; split_bf16(w, hi, lo);
        int elem = sw128(c * 128 + kk * 2) >> 1;
        size_t base = (size_t)(i * 2 + q) * 15360;
        ((__nv_bfloat16*)g_W2sh)[base + elem] = hi;
        ((__nv_bfloat16*)g_W2sl)[base + elem] = lo;
    } else if (idx < totS + totR) {
        int j = idx - totS;
        int kk = j & 63;
        int c  = (j >> 6) % 120;
        int q  = (j / (64 * 120)) % 2;
        int i  = j / (64 * 120 * 2);
        int k  = q * 64 + kk;
        float w = (k < 120) ? res_w[(i*120 + c)*120 + k] : 0.f;
        __nv_bfloat16 hi, lo; split_bf16(w, hi, lo);
        int elem = sw128(c * 128 + kk * 2) >> 1;
        size_t base = (size_t)(i * 2 + q) * 7680;
        ((__nv_bfloat16*)g_W2rh)[base + elem] = hi;
        ((__nv_bfloat16*)g_W2rl)[base + elem] = lo;
    }
}

// head weights: [256 o][64 k] chunks q=0..3, swizzled rows of 128B
__global__ void repack_whead(const float* __restrict__ out_w,
                             const float* __restrict__ end_w) {
    int idx = blockIdx.x * blockDim.x + threadIdx.x;
    const int half = 4 * 256 * 64;
    if (idx >= 2 * half) return;
    int sel = idx / half;
    int j = idx % half;
    int kk = j & 63;
    int n  = (j >> 6) % 256;
    int q  = j / (64 * 256);
    int k  = q * 64 + kk;
    float w;
    if (sel == 0) w = (k < 240) ? out_w[n * 240 + k] : 0.f;
    else          w = end_w[n * 256 + k];
    __nv_bfloat16 hi, lo; split_bf16(w, hi, lo);
    int elem = sw128(n * 128 + kk * 2) >> 1;
    size_t base = (size_t)q * 16384;
    if (sel == 0) {
        ((__nv_bfloat16*)g_Woh)[base + elem] = hi;
        ((__nv_bfloat16*)g_Wol)[base + elem] = lo;
    } else {
        ((__nv_bfloat16*)g_Weh)[base + elem] = hi;
        ((__nv_bfloat16*)g_Wel)[base + elem] = lo;
    }
}

// ---------------- prologues -----------------------------------------------
__global__ void prologue_res(const float* __restrict__ wav,
                             const float* __restrict__ wav_w,
                             const float* __restrict__ wav_b) {
    int idx = blockIdx.x * blockDim.x + threadIdx.x;
    const int total = BB * TLEN * 16;
    if (idx >= total) return;
    int chunk = idx & 15;
    int t = (idx >> 4) % TLEN;
    int b = idx / (TLEN * 16);
    float wv = wav[(size_t)b * TLEN + t];
    U4B uh, ul;
    #pragma unroll
    for (int e = 0; e < 8; e++) {
        int c = chunk * 8 + e;
        float v = (c < RC) ? (wav_w[c] * wv + wav_b[c]) : 0.f;
        split_bf16(v, uh.h[e], ul.h[e]);
    }
    g_resAH[idx] = uh.u;
    g_resAL[idx] = ul.u;
}

__global__ void prologue_cond(const float* __restrict__ cond) {
    int idx = blockIdx.x * blockDim.x + threadIdx.x;
    const int total = BB * TLEN * 16;
    if (idx >= total) return;
    int chunk = idx & 15;
    int t = (idx >> 4) % TLEN;
    int b = idx / (TLEN * 16);
    U4B uh, ul;
    #pragma unroll
    for (int e = 0; e < 8; e++) {
        int c = chunk * 8 + e;
        float v = (c < NM) ? cond[((size_t)b * NM + c) * TLEN + t] : 0.f;
        split_bf16(v, uh.h[e], ul.h[e]);
    }
    g_condH[idx] = uh.u;
    g_condL[idx] = ul.u;
}

// ---------------- mma per-layer kernel (R7 proven: 256 threads) -----------
#define OFF_BA   0        // 240 floats
#define OFF_BB   1024     // 360 floats
#define OFF_XH   4096     // [128][64] bf16 = 16384
#define OFF_XL   20480
#define OFF_WH   36864    // [240][64] bf16 = 30720
#define OFF_WL   67584
#define OFF_RH   98304    // [2][120][64] bf16 = 30720
#define OFF_RL   129024
#define OFF_A2H  159744   // [2][128][64] bf16 = 32768
#define OFF_A2L  192512
#define SMEM_MMA 225280

__global__ void __launch_bounds__(256, 1) block_mma(
    const float* __restrict__ dil_b, const float* __restrict__ cond_b,
    const float* __restrict__ skip_b, const float* __restrict__ res_b,
    int layer, int d, int first, int swap)
{
    extern __shared__ __align__(16) char sm[];
    const uint32_t smb = smem_u32(sm);
    const int tid  = threadIdx.x;
    const int lane = tid & 31;
    const int wid  = tid >> 5;
    const int mw   = wid >> 1;            // 0..3 (m)
    const int nw   = wid & 1;             // 0..1 (n)
    const int b    = blockIdx.y;
    const int t0   = blockIdx.x * 128;

    const uint4* resInH = swap ? g_resBH : g_resAH;
    const uint4* resInL = swap ? g_resBL : g_resAL;
    uint4* resOutH = swap ? g_resAH : g_resBH;
    uint4* resOutL = swap ? g_resAL : g_resBL;

    float* biasA = (float*)(sm + OFF_BA);
    float* biasB = (float*)(sm + OFF_BB);
    for (int e = tid; e < 240; e += 256)
        biasA[e] = dil_b[layer * 240 + e] + cond_b[layer * 240 + e];
    for (int e = tid; e < 360; e += 256)
        biasB[e] = (e < 240) ? skip_b[layer * 240 + e] : res_b[layer * 120 + e - 240];
    // zero-pad phase2 A region B: k 56..63 (p 120..127)
    if (tid < 128) {
        uint32_t byte = tid * 128 + ((7u ^ (tid & 7)) << 4);
        *(uint4*)(sm + OFF_A2H + 16384 + byte) = make_uint4(0, 0, 0, 0);
        *(uint4*)(sm + OFF_A2L + 16384 + byte) = make_uint4(0, 0, 0, 0);
    }

    // ========== phase 1: g[128t x 240n(permuted)], K=384 ==========
    float ac[2][15][4];
    #pragma unroll
    for (int mt = 0; mt < 2; mt++)
        #pragma unroll
        for (int nt = 0; nt < 15; nt++)
            #pragma unroll
            for (int e = 0; e < 4; e++) ac[mt][nt][e] = 0.f;

    for (int q = 0; q < 6; q++) {
        __syncthreads();
        {   // stage X chunk [128][64] hi/lo
            const uint4* srcH; const uint4* srcL; int tshift, half;
            if (q < 2)      { srcH = resInH; srcL = resInL; tshift = t0 - d; half = q; }
            else if (q < 4) { srcH = resInH; srcL = resInL; tshift = t0;     half = q - 2; }
            else            { srcH = g_condH; srcL = g_condL; tshift = t0;   half = q - 4; }
            for (int e = tid; e < 1024; e += 256) {
                int r = e >> 3, ii = e & 7;
                int t = tshift + r;
                uint4 vh = make_uint4(0,0,0,0), vl = make_uint4(0,0,0,0);
                if (t >= 0) {
                    size_t si = ((size_t)b * TLEN + t) * 16 + half * 8 + ii;
                    vh = srcH[si]; vl = srcL[si];
                }
                uint32_t byte = sw128((r << 7) + (ii << 4));
                *(uint4*)(sm + OFF_XH + byte) = vh;
                *(uint4*)(sm + OFF_XL + byte) = vl;
            }
            size_t wb = (size_t)(layer * 6 + q) * 1920;
            for (int e = tid; e < 1920; e += 256) {
                ((uint4*)(sm + OFF_WH))[e] = g_W1h[wb + e];
                ((uint4*)(sm + OFF_WL))[e] = g_W1l[wb + e];
            }
        }
        __syncthreads();
        #pragma unroll
        for (int kt = 0; kt < 4; kt++) {
            uint32_t ah[2][4], al[2][4];
            #pragma unroll
            for (int mt = 0; mt < 2; mt++) {
                int ar = mw * 32 + mt * 16 + (lane & 15);
                int ack = kt * 2 + (lane >> 4);
                uint32_t ab = ar * 128 + (((uint32_t)(ack ^ (ar & 7))) << 4);
                ldsm_x4(ah[mt], smb + OFF_XH + ab);
                ldsm_x4(al[mt], smb + OFF_XL + ab);
            }
            int bn = nw * 120 + (lane & 7);
            int bsel = (lane >> 3) & 1;
            #pragma unroll
            for (int nt = 0; nt < 15; nt++) {
                int n = bn + nt * 8;
                int bck = kt * 2 + bsel;
                uint32_t bb = n * 128 + (((uint32_t)(bck ^ (n & 7))) << 4);
                uint32_t bh[2], bl[2];
                ldsm_x2(bh, smb + OFF_WH + bb);
                ldsm_x2(bl, smb + OFF_WL + bb);
                #pragma unroll
                for (int mt = 0; mt < 2; mt++) {
                    mma16816(ac[mt][nt], ah[mt], bh[0], bh[1]);
                    mma16816(ac[mt][nt], ah[mt], bl[0], bl[1]);
                    mma16816(ac[mt][nt], al[mt], bh[0], bh[1]);
                }
            }
        }
    }

    // ========== gating (in registers) -> phase2 A tile ==========
    #pragma unroll
    for (int nt = 0; nt < 15; nt++) {
        int p = nw * 60 + nt * 4 + (lane & 3);
        int reg = (p < 64) ? 0 : 1;
        int p2 = p & 63;
        float ba_t = biasA[p];
        float ba_s = biasA[p + 120];
        #pragma unroll
        for (int mt = 0; mt < 2; mt++) {
            #pragma unroll
            for (int rh = 0; rh < 2; rh++) {
                int r = mw * 32 + mt * 16 + (lane >> 2) + rh * 8;
                float gt = ac[mt][nt][rh * 2 + 0] + ba_t;
                float gs = ac[mt][nt][rh * 2 + 1] + ba_s;
                float v = fast_tanh(gt) * fast_sigmoid(gs);
                __nv_bfloat16 hi, lo; split_bf16(v, hi, lo);
                uint32_t byte = r * 128 + (((uint32_t)((p2 >> 3) ^ (r & 7))) << 4)
                              + (p2 & 7) * 2;
                *(__nv_bfloat16*)(sm + OFF_A2H + reg * 16384 + byte) = hi;
                *(__nv_bfloat16*)(sm + OFF_A2L + reg * 16384 + byte) = lo;
            }
        }
    }

    // ========== phase 2a: skip[128t x 240c], K=120 ==========
    float sk[2][15][4];
    #pragma unroll
    for (int mt = 0; mt < 2; mt++)
        #pragma unroll
        for (int nt = 0; nt < 15; nt++)
            #pragma unroll
            for (int e = 0; e < 4; e++) sk[mt][nt][e] = 0.f;

    for (int q2 = 0; q2 < 2; q2++) {
        __syncthreads();
        {
            size_t bs = (size_t)(layer * 2 + q2) * 1920;
            size_t br = (size_t)(layer * 2 + q2) * 960;
            for (int e = tid; e < 1920; e += 256) {
                ((uint4*)(sm + OFF_WH))[e] = g_W2sh[bs + e];
                ((uint4*)(sm + OFF_WL))[e] = g_W2sl[bs + e];
            }
            for (int e = tid; e < 960; e += 256) {
                ((uint4*)(sm + OFF_RH + q2 * 15360))[e] = g_W2rh[br + e];
                ((uint4*)(sm + OFF_RL + q2 * 15360))[e] = g_W2rl[br + e];
            }
        }
        __syncthreads();
        #pragma unroll
        for (int kt = 0; kt < 4; kt++) {
            uint32_t ah[2][4], al[2][4];
            #pragma unroll
            for (int mt = 0; mt < 2; mt++) {
                int ar = mw * 32 + mt * 16 + (lane & 15);
                int ack = kt * 2 + (lane >> 4);
                uint32_t ab = ar * 128 + (((uint32_t)(ack ^ (ar & 7))) << 4);
                ldsm_x4(ah[mt], smb + OFF_A2H + q2 * 16384 + ab);
                ldsm_x4(al[mt], smb + OFF_A2L + q2 * 16384 + ab);
            }
            int bn = nw * 120 + (lane & 7);
            int bsel = (lane >> 3) & 1;
            #pragma unroll
            for (int nt = 0; nt < 15; nt++) {
                int n = bn + nt * 8;
                int bck = kt * 2 + bsel;
                uint32_t bb = n * 128 + (((uint32_t)(bck ^ (n & 7))) << 4);
                uint32_t bh[2], bl[2];
                ldsm_x2(bh, smb + OFF_WH + bb);
                ldsm_x2(bl, smb + OFF_WL + bb);
                #pragma unroll
                for (int mt = 0; mt < 2; mt++) {
                    mma16816(sk[mt][nt], ah[mt], bh[0], bh[1]);
                    mma16816(sk[mt][nt], ah[mt], bl[0], bl[1]);
                    mma16816(sk[mt][nt], al[mt], bh[0], bh[1]);
                }
            }
        }
    }

    // skip epilogue: [b][t][240] fp32 accumulate
    #pragma unroll
    for (int nt = 0; nt < 15; nt++) {
        int c = nw * 120 + nt * 8 + 2 * (lane & 3);
        float b0 = biasB[c], b1 = biasB[c + 1];
        #pragma unroll
        for (int mt = 0; mt < 2; mt++) {
            #pragma unroll
            for (int rh = 0; rh < 2; rh++) {
                int t = t0 + mw * 32 + mt * 16 + (lane >> 2) + rh * 8;
                size_t gi = ((size_t)b * TLEN + t) * 240 + c;
                float2 v;
                v.x = sk[mt][nt][rh * 2 + 0] + b0;
                v.y = sk[mt][nt][rh * 2 + 1] + b1;
                if (!first) {
                    float2 o = *(float2*)(g_skip + gi);
                    v.x += o.x; v.y += o.y;
                }
                *(float2*)(g_skip + gi) = v;
            }
        }
    }

    // ========== phase 2b: res[128t x 120c], K=120 ==========
    {
        float rs[2][8][4];
        #pragma unroll
        for (int mt = 0; mt < 2; mt++)
            #pragma unroll
            for (int nt = 0; nt < 8; nt++)
                #pragma unroll
                for (int e = 0; e < 4; e++) rs[mt][nt][e] = 0.f;
        const int NT = 8 - nw;

        for (int q2 = 0; q2 < 2; q2++) {
            #pragma unroll
            for (int kt = 0; kt < 4; kt++) {
                uint32_t ah[2][4], al[2][4];
                #pragma unroll
                for (int mt = 0; mt < 2; mt++) {
                    int ar = mw * 32 + mt * 16 + (lane & 15);
                    int ack = kt * 2 + (lane >> 4);
                    uint32_t ab = ar * 128 + (((uint32_t)(ack ^ (ar & 7))) << 4);
                    ldsm_x4(ah[mt], smb + OFF_A2H + q2 * 16384 + ab);
                    ldsm_x4(al[mt], smb + OFF_A2L + q2 * 16384 + ab);
                }
                int bn = nw * 64 + (lane & 7);
                int bsel = (lane >> 3) & 1;
                #pragma unroll
                for (int nt = 0; nt < 8; nt++) {
                    if (nt < NT) {
                        int n = bn + nt * 8;
                        int bck = kt * 2 + bsel;
                        uint32_t bb = n * 128 + (((uint32_t)(bck ^ (n & 7))) << 4);
                        uint32_t bh[2], bl[2];
                        ldsm_x2(bh, smb + OFF_RH + q2 * 15360 + bb);
                        ldsm_x2(bl, smb + OFF_RL + q2 * 15360 + bb);
                        #pragma unroll
                        for (int mt = 0; mt < 2; mt++) {
                            mma16816(rs[mt][nt], ah[mt], bh[0], bh[1]);
                            mma16816(rs[mt][nt], ah[mt], bl[0], bl[1]);
                            mma16816(rs[mt][nt], al[mt], bh[0], bh[1]);
                        }
                    }
                }
            }
        }

        // res epilogue
        const uint32_t* rInH = (const uint32_t*)resInH;
        const uint32_t* rInL = (const uint32_t*)resInL;
        uint32_t* rOutH = (uint32_t*)resOutH;
        uint32_t* rOutL = (uint32_t*)resOutL;
        #pragma unroll
        for (int nt = 0; nt < 8; nt++) {
            if (nt < NT) {
                int c = nw * 64 + nt * 8 + 2 * (lane & 3);
                float b0 = biasB[240 + c], b1 = biasB[240 + c + 1];
                #pragma unroll
                for (int mt = 0; mt < 2; mt++) {
                    #pragma unroll
                    for (int rh = 0; rh < 2; rh++) {
                        int t = t0 + mw * 32 + mt * 16 + (lane >> 2) + rh * 8;
                        size_t ri = ((size_t)b * TLEN + t) * 64 + (c >> 1);
                        U1B vh, vl, oh, ol;
                        vh.u = rInH[ri]; vl.u = rInL[ri];
                        float o0 = rs[mt][nt][rh * 2 + 0] + b0
                                 + __bfloat162float(vh.h[0]) + __bfloat162float(vl.h[0]);
                        float o1 = rs[mt][nt][rh * 2 + 1] + b1
                                 + __bfloat162float(vh.h[1]) + __bfloat162float(vl.h[1]);
                        split_bf16(o0, oh.h[0], ol.h[0]);
                        split_bf16(o1, oh.h[1], ol.h[1]);
                        rOutH[ri] = oh.u;
                        rOutL[ri] = ol.u;
                    }
                }
            }
        }
    }
    // zero pad channels 120-127 of resOut
    if (tid < 128) {
        size_t rp = ((size_t)b * TLEN + t0 + tid) * 16 + 15;
        resOutH[rp] = make_uint4(0, 0, 0, 0);
        resOutL[rp] = make_uint4(0, 0, 0, 0);
    }
}

// ---------------- fused mma head kernel -----------------------------------
// smem layout (bytes):
#define HOFF_OB   0        // out_b 256 floats
#define HOFF_EB   1024     // end_b 256 floats
#define HOFF_A1H  2048     // [128][64] bf16 = 16384
#define HOFF_A1L  18432
#define HOFF_WHH  34816    // [256][64] bf16 = 32768
#define HOFF_WHL  67584
#define HOFF_A2H  100352   // [4][128][64] bf16 = 65536
#define HOFF_A2L  165888
#define SMEM_HEAD 231424

__global__ void __launch_bounds__(256, 1) head_mma(
    const float* __restrict__ out_b, const float* __restrict__ end_b,
    float* __restrict__ out)
{
    extern __shared__ __align__(16) char sm[];
    const uint32_t smb = smem_u32(sm);
    const int tid  = threadIdx.x;
    const int lane = tid & 31;
    const int wid  = tid >> 5;
    const int mw   = wid >> 1;            // 0..3
    const int nw   = wid & 1;             // 0..1
    const int b    = blockIdx.y;
    const int t0   = blockIdx.x * 128;

    float* obs = (float*)(sm + HOFF_OB);
    float* ebs = (float*)(sm + HOFF_EB);
    for (int e = tid; e < 256; e += 256) { obs[e] = out_b[e]; ebs[e] = end_b[e]; }

    // ===== gemm1: o[128t x 256o] = relu(skip) @ Wo^T, K=240(pad 256) =====
    float ac[2][16][4];
    #pragma unroll
    for (int mt = 0; mt < 2; mt++)
        #pragma unroll
        for (int nt = 0; nt < 16; nt++)
            #pragma unroll
            for (int e = 0; e < 4; e++) ac[mt][nt][e] = 0.f;

    for (int q = 0; q < 4; q++) {
        __syncthreads();
        // stage A1: relu(g_skip) chunk [128][64] -> hi/lo swizzled
        for (int e = tid; e < 1024; e += 256) {
            int r = e >> 3, ii = e & 7;
            int c0 = q * 64 + ii * 8;
            U4B uh, ul;
            if (c0 < 240) {
                size_t gi = ((size_t)b * TLEN + t0 + r) * 240 + c0;
                float4 v0 = *(const float4*)(g_skip + gi);
                float4 v1 = *(const float4*)(g_skip + gi + 4);
                float vv[8] = {v0.x, v0.y, v0.z, v0.w, v1.x, v1.y, v1.z, v1.w};
                #pragma unroll
                for (int k = 0; k < 8; k++)
                    split_bf16(fmaxf(vv[k], 0.f), uh.h[k], ul.h[k]);
            } else {
                uh.u = make_uint4(0,0,0,0); ul.u = make_uint4(0,0,0,0);
            }
            uint32_t byte = sw128((r << 7) + (ii << 4));
            *(uint4*)(sm + HOFF_A1H + byte) = uh.u;
            *(uint4*)(sm + HOFF_A1L + byte) = ul.u;
        }
        // stage Wo chunk [256][64] hi/lo
        for (int e = tid; e < 2048; e += 256) {
            ((uint4*)(sm + HOFF_WHH))[e] = g_Woh[q * 2048 + e];
            ((uint4*)(sm + HOFF_WHL))[e] = g_Wol[q * 2048 + e];
        }
        __syncthreads();
        #pragma unroll
        for (int kt = 0; kt < 4; kt++) {
            uint32_t ah[2][4], al[2][4];
            #pragma unroll
            for (int mt = 0; mt < 2; mt++) {
                int ar = mw * 32 + mt * 16 + (lane & 15);
                int ack = kt * 2 + (lane >> 4);
                uint32_t ab = ar * 128 + (((uint32_t)(ack ^ (ar & 7))) << 4);
                ldsm_x4(ah[mt], smb + HOFF_A1H + ab);
                ldsm_x4(al[mt], smb + HOFF_A1L + ab);
            }
            int bn = nw * 128 + (lane & 7);
            int bsel = (lane >> 3) & 1;
            #pragma unroll
            for (int nt = 0; nt < 16; nt++) {
                int n = bn + nt * 8;
                int bck = kt * 2 + bsel;
                uint32_t bb = n * 128 + (((uint32_t)(bck ^ (n & 7))) << 4);
                uint32_t bh[2], bl[2];
                ldsm_x2(bh, smb + HOFF_WHH + bb);
                ldsm_x2(bl, smb + HOFF_WHL + bb);
                #pragma unroll
                for (int mt = 0; mt < 2; mt++) {
                    mma16816(ac[mt][nt], ah[mt], bh[0], bh[1]);
                    mma16816(ac[mt][nt], ah[mt], bl[0], bl[1]);
                    mma16816(ac[mt][nt], al[mt], bh[0], bh[1]);
                }
            }
        }
    }

    // ===== relu(o + out_b) -> A2 smem (4 k-chunks, swizzled, hi/lo) =====
    __syncthreads();   // protect W buffer reads done; A2 region writes next
    #pragma unroll
    for (int nt = 0; nt < 16; nt++) {
        int p = nw * 128 + nt * 8 + 2 * (lane & 3);
        int chunk = p >> 6;
        int p2 = p & 63;
        float b0 = obs[p], b1 = obs[p + 1];
        #pragma unroll
        for (int mt = 0; mt < 2; mt++) {
            #pragma unroll
            for (int rh = 0; rh < 2; rh++) {
                int r = mw * 32 + mt * 16 + (lane >> 2) + rh * 8;
                float v0 = fmaxf(ac[mt][nt][rh * 2 + 0] + b0, 0.f);
                float v1 = fmaxf(ac[mt][nt][rh * 2 + 1] + b1, 0.f);
                U1B ph, pl;
                split_bf16(v0, ph.h[0], pl.h[0]);
                split_bf16(v1, ph.h[1], pl.h[1]);
                uint32_t byte = r * 128 + (((uint32_t)((p2 >> 3) ^ (r & 7))) << 4)
                              + (p2 & 7) * 2;
                *(uint32_t*)(sm + HOFF_A2H + chunk * 16384 + byte) = ph.u;
                *(uint32_t*)(sm + HOFF_A2L + chunk * 16384 + byte) = pl.u;
            }
        }
    }

    // ===== gemm2: end[128t x 256o] = relu(o) @ We^T, K=256 =====
    #pragma unroll
    for (int mt = 0; mt < 2; mt++)
        #pragma unroll
        for (int nt = 0; nt < 16; nt++)
            #pragma unroll
            for (int e = 0; e < 4; e++) ac[mt][nt][e] = 0.f;

    for (int q = 0; q < 4; q++) {
        __syncthreads();
        for (int e = tid; e < 2048; e += 256) {
            ((uint4*)(sm + HOFF_WHH))[e] = g_Weh[q * 2048 + e];
            ((uint4*)(sm + HOFF_WHL))[e] = g_Wel[q * 2048 + e];
        }
        __syncthreads();
        #pragma unroll
        for (int kt = 0; kt < 4; kt++) {
            uint32_t ah[2][4], al[2][4];
            #pragma unroll
            for (int mt = 0; mt < 2; mt++) {
                int ar = mw * 32 + mt * 16 + (lane & 15);
                int ack = kt * 2 + (lane >> 4);
                uint32_t ab = ar * 128 + (((uint32_t)(ack ^ (ar & 7))) << 4);
                ldsm_x4(ah[mt], smb + HOFF_A2H + q * 16384 + ab);
                ldsm_x4(al[mt], smb + HOFF_A2L + q * 16384 + ab);
            }
            int bn = nw * 128 + (lane & 7);
            int bsel = (lane >> 3) & 1;
            #pragma unroll
            for (int nt = 0; nt < 16; nt++) {
                int n = bn + nt * 8;
                int bck = kt * 2 + bsel;
                uint32_t bb = n * 128 + (((uint32_t)(bck ^ (n & 7))) << 4);
                uint32_t bh[2], bl[2];
                ldsm_x2(bh, smb + HOFF_WHH + bb);
                ldsm_x2(bl, smb + HOFF_WHL + bb);
                #pragma unroll
                for (int mt = 0; mt < 2; mt++) {
                    mma16816(ac[mt][nt], ah[mt], bh[0], bh[1]);
                    mma16816(ac[mt][nt], ah[mt], bl[0], bl[1]);
                    mma16816(ac[mt][nt], al[mt], bh[0], bh[1]);
                }
            }
        }
    }

    // ===== output: out[b][o][t] = ac + end_b =====
    #pragma unroll
    for (int nt = 0; nt < 16; nt++) {
        int o0 = nw * 128 + nt * 8 + 2 * (lane & 3);
        float b0 = ebs[o0], b1 = ebs[o0 + 1];
        #pragma unroll
        for (int mt = 0; mt < 2; mt++) {
            #pragma unroll
            for (int rh = 0; rh < 2; rh++) {
                int t = t0 + mw * 32 + mt * 16 + (lane >> 2) + rh * 8;
                out[((size_t)b * NC + o0) * TLEN + t]     = ac[mt][nt][rh * 2 + 0] + b0;
                out[((size_t)b * NC + o0 + 1) * TLEN + t] = ac[mt][nt][rh * 2 + 1] + b1;
            }
        }
    }
}

// ---------------- host launcher -------------------------------------------
extern "C" void kernel_launch(void* const* d_in, const int* in_sizes, int n_in,
                              void* d_out, int out_size) {
    const float* wav    = (const float*)d_in[0];
    const float* cond   = (const float*)d_in[1];
    const float* wav_w  = (const float*)d_in[2];
    const float* wav_b  = (const float*)d_in[3];
    const float* cond_w = (const float*)d_in[4];
    const float* cond_b = (const float*)d_in[5];
    const float* dil_w  = (const float*)d_in[6];
    const float* dil_b  = (const float*)d_in[7];
    const float* skip_w = (const float*)d_in[8];
    const float* skip_b = (const float*)d_in[9];
    const float* res_w  = (const float*)d_in[10];
    const float* res_b  = (const float*)d_in[11];
    const float* out_w  = (const float*)d_in[12];
    const float* out_b  = (const float*)d_in[13];
    const float* end_w  = (const float*)d_in[14];
    const float* end_b  = (const float*)d_in[15];

    cudaFuncSetAttribute(block_mma, cudaFuncAttributeMaxDynamicSharedMemorySize,
                         SMEM_MMA);
    cudaFuncSetAttribute(head_mma, cudaFuncAttributeMaxDynamicSharedMemorySize,
                         SMEM_HEAD);

    repack_w1<<<(NBLK * 6 * 240 * 64 + 255) / 256, 256>>>(dil_w, cond_w);
    repack_w2<<<(NBLK * 2 * (240 + 120) * 64 + 255) / 256, 256>>>(skip_w, res_w);
    repack_whead<<<(2 * 4 * 256 * 64 + 255) / 256, 256>>>(out_w, end_w);
    prologue_res<<<(BB * TLEN * 16 + 255) / 256, 256>>>(wav, wav_w, wav_b);
    prologue_cond<<<(BB * TLEN * 16 + 255) / 256, 256>>>(cond);

    dim3 gridB(TLEN / 128, BB);
    for (int i = 0; i < NBLK; i++) {
        int d = 1 << (i % 8);
        block_mma<<<gridB, 256, SMEM_MMA>>>(dil_b, cond_b, skip_b, res_b,
                                            i, d, (i == 0) ? 1 : 0, i & 1);
    }
    head_mma<<<gridB, 256, SMEM_HEAD>>>(out_b, end_b, (float*)d_out);
}

// round 10
// speedup vs baseline: 1.4736x; 1.1542x over previous
#include <cuda_runtime.h>
#include <cuda_bf16.h>
#include <math.h>
#include <stdint.h>

#define BB   4
#define TLEN 32768
#define NM   80
#define RC   120
#define SC   240
#define NBLK 16
#define NC   256

// ---------------- device scratch (no allocations allowed) ----------------
__device__ uint4 g_resAH[BB * TLEN * 16];
__device__ uint4 g_resAL[BB * TLEN * 16];
__device__ uint4 g_resBH[BB * TLEN * 16];
__device__ uint4 g_resBL[BB * TLEN * 16];
__device__ uint4 g_condH[BB * TLEN * 16];
__device__ uint4 g_condL[BB * TLEN * 16];
__device__ float g_skip [BB * TLEN * SC];   // [b][t][c]
__device__ uint4 g_W1h[NBLK * 6 * 1920];    // phase1, rows = permuted n (240)
__device__ uint4 g_W1l[NBLK * 6 * 1920];
__device__ uint4 g_W2sh[NBLK * 2 * 1920];   // skip [240][64]
__device__ uint4 g_W2sl[NBLK * 2 * 1920];
__device__ uint4 g_W2rh[NBLK * 2 * 960];    // res  [120][64]
__device__ uint4 g_W2rl[NBLK * 2 * 960];
__device__ uint4 g_Woh[4 * 2048];           // out_w [256][64] chunks, swizzled
__device__ uint4 g_Wol[4 * 2048];
__device__ uint4 g_Weh[4 * 2048];           // end_w [256][64] chunks, swizzled
__device__ uint4 g_Wel[4 * 2048];

// ---------------- helpers -------------------------------------------------
__device__ __forceinline__ uint32_t smem_u32(const void* p) {
    uint32_t a;
    asm("{ .reg .u64 t; cvta.to.shared.u64 t, %1; cvt.u32.u64 %0, t; }"
        : "=r"(a) : "l"(p));
    return a;
}
__device__ __forceinline__ uint32_t sw128(uint32_t b) { return b ^ ((b >> 3) & 0x70); }

union U4B { uint4 u; __nv_bfloat16 h[8]; };
union U1B { uint32_t u; __nv_bfloat16 h[2]; };

__device__ __forceinline__ void split_bf16(float x, __nv_bfloat16& hi, __nv_bfloat16& lo) {
    hi = __float2bfloat16(x);
    lo = __float2bfloat16(x - __bfloat162float(hi));
}
__device__ __forceinline__ float fast_tanh(float x) {
    return 1.f - 2.f / (1.f + __expf(2.f * x));
}
__device__ __forceinline__ float fast_sigmoid(float x) {
    return 1.f / (1.f + __expf(-x));
}

__device__ __forceinline__ void ldsm_x4(uint32_t* r, uint32_t addr) {
    asm volatile("ldmatrix.sync.aligned.m8n8.x4.shared.b16 {%0,%1,%2,%3}, [%4];"
                 : "=r"(r[0]), "=r"(r[1]), "=r"(r[2]), "=r"(r[3]) : "r"(addr));
}
__device__ __forceinline__ void ldsm_x2(uint32_t* r, uint32_t addr) {
    asm volatile("ldmatrix.sync.aligned.m8n8.x2.shared.b16 {%0,%1}, [%2];"
                 : "=r"(r[0]), "=r"(r[1]) : "r"(addr));
}
__device__ __forceinline__ void mma16816(float* c, const uint32_t* a,
                                         uint32_t b0, uint32_t b1) {
    asm volatile("mma.sync.aligned.m16n8k16.row.col.f32.bf16.bf16.f32 "
                 "{%0,%1,%2,%3}, {%4,%5,%6,%7}, {%8,%9}, {%0,%1,%2,%3};"
                 : "+f"(c[0]), "+f"(c[1]), "+f"(c[2]), "+f"(c[3])
                 : "r"(a[0]), "r"(a[1]), "r"(a[2]), "r"(a[3]), "r"(b0), "r"(b1));
}
__device__ __forceinline__ void cpa16(uint32_t smem, const void* gmem, uint32_t ssz) {
    asm volatile("cp.async.cg.shared.global [%0], [%1], 16, %2;"
                 :: "r"(smem), "l"(gmem), "r"(ssz) : "memory");
}
#define CPA_COMMIT() asm volatile("cp.async.commit_group;" ::: "memory")
template <int N> __device__ __forceinline__ void cpa_wait() {
    asm volatile("cp.async.wait_group %0;" :: "n"(N) : "memory");
}

// ---------------- weight repack kernels -----------------------------------
__global__ void repack_w1(const float* __restrict__ dil_w,
                          const float* __restrict__ cond_w) {
    int idx = blockIdx.x * blockDim.x + threadIdx.x;
    const int total = NBLK * 6 * 240 * 64;
    if (idx >= total) return;
    int kk = idx & 63;
    int n  = (idx >> 6) % 240;
    int q  = (idx / (64 * 240)) % 6;
    int i  = idx / (64 * 240 * 6);
    int c  = (n >> 1) + (n & 1) * 120;          // original output channel
    int kc = (q & 1) * 64 + kk;
    float w = 0.f;
    if (q < 2)      { if (kc < 120) w = dil_w[((i*240 + c)*120 + kc)*2 + 0]; }
    else if (q < 4) { if (kc < 120) w = dil_w[((i*240 + c)*120 + kc)*2 + 1]; }
    else            { if (kc < 80)  w = cond_w[(i*240 + c)*80 + kc]; }
    __nv_bfloat16 hi, lo; split_bf16(w, hi, lo);
    int elem = sw128(n * 128 + kk * 2) >> 1;
    size_t base = (size_t)(i * 6 + q) * 15360;
    ((__nv_bfloat16*)g_W1h)[base + elem] = hi;
    ((__nv_bfloat16*)g_W1l)[base + elem] = lo;
}

__global__ void repack_w2(const float* __restrict__ skip_w,
                          const float* __restrict__ res_w) {
    int idx = blockIdx.x * blockDim.x + threadIdx.x;
    const int totS = NBLK * 2 * 240 * 64;
    const int totR = NBLK * 2 * 120 * 64;
    if (idx < totS) {
        int kk = idx & 63;
        int c  = (idx >> 6) % 240;
        int q  = (idx / (64 * 240)) % 2;
        int i  = idx / (64 * 240 * 2);
        int k  = q * 64 + kk;
        float w = (k < 120) ? skip_w[(i*240 + c)*120 + k] : 0.f;
        __nv_bfloat16 hi, lo; split_bf16(w, hi, lo);
        int elem = sw128(c * 128 + kk * 2) >> 1;
        size_t base = (size_t)(i * 2 + q) * 15360;
        ((__nv_bfloat16*)g_W2sh)[base + elem] = hi;
        ((__nv_bfloat16*)g_W2sl)[base + elem] = lo;
    } else if (idx < totS + totR) {
        int j = idx - totS;
        int kk = j & 63;
        int c  = (j >> 6) % 120;
        int q  = (j / (64 * 120)) % 2;
        int i  = j / (64 * 120 * 2);
        int k  = q * 64 + kk;
        float w = (k < 120) ? res_w[(i*120 + c)*120 + k] : 0.f;
        __nv_bfloat16 hi, lo; split_bf16(w, hi, lo);
        int elem = sw128(c * 128 + kk * 2) >> 1;
        size_t base = (size_t)(i * 2 + q) * 7680;
        ((__nv_bfloat16*)g_W2rh)[base + elem] = hi;
        ((__nv_bfloat16*)g_W2rl)[base + elem] = lo;
    }
}

// head weights: [256 o][64 k] chunks q=0..3, swizzled rows of 128B
__global__ void repack_whead(const float* __restrict__ out_w,
                             const float* __restrict__ end_w) {
    int idx = blockIdx.x * blockDim.x + threadIdx.x;
    const int half = 4 * 256 * 64;
    if (idx >= 2 * half) return;
    int sel = idx / half;
    int j = idx % half;
    int kk = j & 63;
    int n  = (j >> 6) % 256;
    int q  = j / (64 * 256);
    int k  = q * 64 + kk;
    float w;
    if (sel == 0) w = (k < 240) ? out_w[n * 240 + k] : 0.f;
    else          w = end_w[n * 256 + k];
    __nv_bfloat16 hi, lo; split_bf16(w, hi, lo);
    int elem = sw128(n * 128 + kk * 2) >> 1;
    size_t base = (size_t)q * 16384;
    if (sel == 0) {
        ((__nv_bfloat16*)g_Woh)[base + elem] = hi;
        ((__nv_bfloat16*)g_Wol)[base + elem] = lo;
    } else {
        ((__nv_bfloat16*)g_Weh)[base + elem] = hi;
        ((__nv_bfloat16*)g_Wel)[base + elem] = lo;
    }
}

// ---------------- prologues -----------------------------------------------
__global__ void prologue_res(const float* __restrict__ wav,
                             const float* __restrict__ wav_w,
                             const float* __restrict__ wav_b) {
    int idx = blockIdx.x * blockDim.x + threadIdx.x;
    const int total = BB * TLEN * 16;
    if (idx >= total) return;
    int chunk = idx & 15;
    int t = (idx >> 4) % TLEN;
    int b = idx / (TLEN * 16);
    float wv = wav[(size_t)b * TLEN + t];
    U4B uh, ul;
    #pragma unroll
    for (int e = 0; e < 8; e++) {
        int c = chunk * 8 + e;
        float v = (c < RC) ? (wav_w[c] * wv + wav_b[c]) : 0.f;
        split_bf16(v, uh.h[e], ul.h[e]);
    }
    g_resAH[idx] = uh.u;
    g_resAL[idx] = ul.u;
}

__global__ void prologue_cond(const float* __restrict__ cond) {
    int idx = blockIdx.x * blockDim.x + threadIdx.x;
    const int total = BB * TLEN * 16;
    if (idx >= total) return;
    int chunk = idx & 15;
    int t = (idx >> 4) % TLEN;
    int b = idx / (TLEN * 16);
    U4B uh, ul;
    #pragma unroll
    for (int e = 0; e < 8; e++) {
        int c = chunk * 8 + e;
        float v = (c < NM) ? cond[((size_t)b * NM + c) * TLEN + t] : 0.f;
        split_bf16(v, uh.h[e], ul.h[e]);
    }
    g_condH[idx] = uh.u;
    g_condL[idx] = ul.u;
}

// ---------------- mma per-layer kernel (cp.async pipelined) ---------------
// smem: bias 4KB | X dbl-buf 2x32KB (A2 in phase2) | W dbl-buf 2x60KB
#define OFF_BA   0
#define OFF_BB   1024
#define OFF_X    4096
#define XBUF(i)  (OFF_X + (i) * 32768)          // XH at +0, XL at +16384
#define OFF_W    69632
#define WBUF(i)  (OFF_W + (i) * 61440)          // H at +0, L at +30720
#define SMEM_MMA 192512

__global__ void __launch_bounds__(256, 1) block_mma(
    const float* __restrict__ dil_b, const float* __restrict__ cond_b,
    const float* __restrict__ skip_b, const float* __restrict__ res_b,
    int layer, int d, int first, int swap)
{
    extern __shared__ __align__(16) char sm[];
    const uint32_t smb = smem_u32(sm);
    const int tid  = threadIdx.x;
    const int lane = tid & 31;
    const int wid  = tid >> 5;
    const int mw   = wid >> 1;            // 0..3 (m)
    const int nw   = wid & 1;             // 0..1 (n)
    const int b    = blockIdx.y;
    const int t0   = blockIdx.x * 128;

    const uint4* resInH = swap ? g_resBH : g_resAH;
    const uint4* resInL = swap ? g_resBL : g_resAL;
    uint4* resOutH = swap ? g_resAH : g_resBH;
    uint4* resOutL = swap ? g_resAL : g_resBL;

    // ---- staging helpers (issue cp.async + one commit) ----
    auto stage1 = [&](int q) {
        const uint4* srcH; const uint4* srcL; int tshift, half;
        if (q < 2)      { srcH = resInH; srcL = resInL; tshift = t0 - d; half = q; }
        else if (q < 4) { srcH = resInH; srcL = resInL; tshift = t0;     half = q - 2; }
        else            { srcH = g_condH; srcL = g_condL; tshift = t0;   half = q - 4; }
        uint32_t xb = smb + XBUF(q & 1);
        for (int e = tid; e < 1024; e += 256) {
            int r = e >> 3, ii = e & 7;
            int t = tshift + r;
            uint32_t ok = (t >= 0) ? 16u : 0u;
            int tc = (t >= 0) ? t : 0;
            size_t si = ((size_t)b * TLEN + tc) * 16 + half * 8 + ii;
            uint32_t byte = sw128((r << 7) + (ii << 4));
            cpa16(xb + byte,          srcH + si, ok);
            cpa16(xb + 16384 + byte,  srcL + si, ok);
        }
        uint32_t wb = smb + WBUF(q & 1);
        size_t wgb = (size_t)(layer * 6 + q) * 1920;
        for (int e = tid; e < 1920; e += 256) {
            cpa16(wb + e * 16,          g_W1h + wgb + e, 16);
            cpa16(wb + 30720 + e * 16,  g_W1l + wgb + e, 16);
        }
        CPA_COMMIT();
    };
    auto stage2s = [&](int q2) {
        uint32_t wb = smb + WBUF(q2);
        size_t bs = (size_t)(layer * 2 + q2) * 1920;
        for (int e = tid; e < 1920; e += 256) {
            cpa16(wb + e * 16,          g_W2sh + bs + e, 16);
            cpa16(wb + 30720 + e * 16,  g_W2sl + bs + e, 16);
        }
        CPA_COMMIT();
    };
    auto stage2r = [&](int q2) {
        uint32_t wb = smb + WBUF(q2);
        size_t br = (size_t)(layer * 2 + q2) * 960;
        for (int e = tid; e < 960; e += 256) {
            cpa16(wb + e * 16,          g_W2rh + br + e, 16);
            cpa16(wb + 30720 + e * 16,  g_W2rl + br + e, 16);
        }
        CPA_COMMIT();
    };

    stage1(0);

    float* biasA = (float*)(sm + OFF_BA);
    float* biasB = (float*)(sm + OFF_BB);
    for (int e = tid; e < 240; e += 256)
        biasA[e] = dil_b[layer * 240 + e] + cond_b[layer * 240 + e];
    for (int e = tid; e < 360; e += 256)
        biasB[e] = (e < 240) ? skip_b[layer * 240 + e] : res_b[layer * 120 + e - 240];

    // ========== phase 1: g[128t x 240n(permuted)], K=384 ==========
    float ac[2][15][4];
    #pragma unroll
    for (int mt = 0; mt < 2; mt++)
        #pragma unroll
        for (int nt = 0; nt < 15; nt++)
            #pragma unroll
            for (int e = 0; e < 4; e++) ac[mt][nt][e] = 0.f;

    const int bn   = nw * 120 + (lane & 7);
    const int bhi  = (lane >> 4) << 3;         // pairing: lanes 16-31 -> +8 rows
    const int bsel = (lane >> 3) & 1;

    for (int q = 0; q < 6; q++) {
        if (q < 5) stage1(q + 1);
        else       stage2s(0);
        cpa_wait<1>();
        __syncthreads();
        uint32_t xb  = smb + XBUF(q & 1);
        uint32_t wbh = smb + WBUF(q & 1);
        uint32_t wbl = wbh + 30720;
        #pragma unroll
        for (int kt = 0; kt < 4; kt++) {
            uint32_t ah[2][4], al[2][4];
            #pragma unroll
            for (int mt = 0; mt < 2; mt++) {
                int ar = mw * 32 + mt * 16 + (lane & 15);
                int ack = kt * 2 + (lane >> 4);
                uint32_t ab = ar * 128 + (((uint32_t)(ack ^ (ar & 7))) << 4);
                ldsm_x4(ah[mt], xb + ab);
                ldsm_x4(al[mt], xb + 16384 + ab);
            }
            int bck = kt * 2 + bsel;
            #pragma unroll
            for (int j = 0; j < 7; j++) {
                int n0 = bn + j * 16 + bhi;
                uint32_t bb = n0 * 128 + (((uint32_t)(bck ^ (n0 & 7))) << 4);
                uint32_t bq[4], bl4[4];
                ldsm_x4(bq,  wbh + bb);
                ldsm_x4(bl4, wbl + bb);
                #pragma unroll
                for (int mt = 0; mt < 2; mt++) {
                    mma16816(ac[mt][2*j],   ah[mt], bq[0],  bq[1]);
                    mma16816(ac[mt][2*j],   ah[mt], bl4[0], bl4[1]);
                    mma16816(ac[mt][2*j],   al[mt], bq[0],  bq[1]);
                    mma16816(ac[mt][2*j+1], ah[mt], bq[2],  bq[3]);
                    mma16816(ac[mt][2*j+1], ah[mt], bl4[2], bl4[3]);
                    mma16816(ac[mt][2*j+1], al[mt], bq[2],  bq[3]);
                }
            }
            {   // nt = 14
                int n = nw * 120 + 112 + (lane & 7);
                uint32_t bb = n * 128 + (((uint32_t)(bck ^ (n & 7))) << 4);
                uint32_t bh2[2], bl2[2];
                ldsm_x2(bh2, wbh + bb);
                ldsm_x2(bl2, wbl + bb);
                #pragma unroll
                for (int mt = 0; mt < 2; mt++) {
                    mma16816(ac[mt][14], ah[mt], bh2[0], bh2[1]);
                    mma16816(ac[mt][14], ah[mt], bl2[0], bl2[1]);
                    mma16816(ac[mt][14], al[mt], bh2[0], bh2[1]);
                }
            }
        }
        __syncthreads();
    }

    // ========== gating (registers) -> A2 tile in X buffers ==========
    #pragma unroll
    for (int nt = 0; nt < 15; nt++) {
        int p = nw * 60 + nt * 4 + (lane & 3);
        int reg = (p < 64) ? 0 : 1;
        int p2 = p & 63;
        float ba_t = biasA[p];
        float ba_s = biasA[p + 120];
        #pragma unroll
        for (int mt = 0; mt < 2; mt++) {
            #pragma unroll
            for (int rh = 0; rh < 2; rh++) {
                int r = mw * 32 + mt * 16 + (lane >> 2) + rh * 8;
                float gt = ac[mt][nt][rh * 2 + 0] + ba_t;
                float gs = ac[mt][nt][rh * 2 + 1] + ba_s;
                float v = fast_tanh(gt) * fast_sigmoid(gs);
                __nv_bfloat16 hi, lo; split_bf16(v, hi, lo);
                uint32_t byte = r * 128 + (((uint32_t)((p2 >> 3) ^ (r & 7))) << 4)
                              + (p2 & 7) * 2;
                *(__nv_bfloat16*)(sm + XBUF(reg) + byte) = hi;
                *(__nv_bfloat16*)(sm + XBUF(reg) + 16384 + byte) = lo;
            }
        }
    }
    // zero-pad A2 chunk1 (p 120..127)
    if (tid < 128) {
        uint32_t byte = tid * 128 + ((7u ^ (tid & 7)) << 4);
        *(uint4*)(sm + XBUF(1) + byte)          = make_uint4(0, 0, 0, 0);
        *(uint4*)(sm + XBUF(1) + 16384 + byte)  = make_uint4(0, 0, 0, 0);
    }

    // ========== phase 2a: skip[128t x 240c], K=120 ==========
    float sk[2][15][4];
    #pragma unroll
    for (int mt = 0; mt < 2; mt++)
        #pragma unroll
        for (int nt = 0; nt < 15; nt++)
            #pragma unroll
            for (int e = 0; e < 4; e++) sk[mt][nt][e] = 0.f;

    for (int q2 = 0; q2 < 2; q2++) {
        if (q2 == 0) stage2s(1);
        else         stage2r(0);
        cpa_wait<1>();
        __syncthreads();
        uint32_t xb  = smb + XBUF(q2);
        uint32_t wbh = smb + WBUF(q2);
        uint32_t wbl = wbh + 30720;
        #pragma unroll
        for (int kt = 0; kt < 4; kt++) {
            uint32_t ah[2][4], al[2][4];
            #pragma unroll
            for (int mt = 0; mt < 2; mt++) {
                int ar = mw * 32 + mt * 16 + (lane & 15);
                int ack = kt * 2 + (lane >> 4);
                uint32_t ab = ar * 128 + (((uint32_t)(ack ^ (ar & 7))) << 4);
                ldsm_x4(ah[mt], xb + ab);
                ldsm_x4(al[mt], xb + 16384 + ab);
            }
            int bck = kt * 2 + bsel;
            #pragma unroll
            for (int j = 0; j < 7; j++) {
                int n0 = bn + j * 16 + bhi;
                uint32_t bb = n0 * 128 + (((uint32_t)(bck ^ (n0 & 7))) << 4);
                uint32_t bq[4], bl4[4];
                ldsm_x4(bq,  wbh + bb);
                ldsm_x4(bl4, wbl + bb);
                #pragma unroll
                for (int mt = 0; mt < 2; mt++) {
                    mma16816(sk[mt][2*j],   ah[mt], bq[0],  bq[1]);
                    mma16816(sk[mt][2*j],   ah[mt], bl4[0], bl4[1]);
                    mma16816(sk[mt][2*j],   al[mt], bq[0],  bq[1]);
                    mma16816(sk[mt][2*j+1], ah[mt], bq[2],  bq[3]);
                    mma16816(sk[mt][2*j+1], ah[mt], bl4[2], bl4[3]);
                    mma16816(sk[mt][2*j+1], al[mt], bq[2],  bq[3]);
                }
            }
            {
                int n = nw * 120 + 112 + (lane & 7);
                uint32_t bb = n * 128 + (((uint32_t)(bck ^ (n & 7))) << 4);
                uint32_t bh2[2], bl2[2];
                ldsm_x2(bh2, wbh + bb);
                ldsm_x2(bl2, wbl + bb);
                #pragma unroll
                for (int mt = 0; mt < 2; mt++) {
                    mma16816(sk[mt][14], ah[mt], bh2[0], bh2[1]);
                    mma16816(sk[mt][14], ah[mt], bl2[0], bl2[1]);
                    mma16816(sk[mt][14], al[mt], bh2[0], bh2[1]);
                }
            }
        }
        __syncthreads();
    }

    // skip epilogue: [b][t][240] fp32 accumulate
    #pragma unroll
    for (int nt = 0; nt < 15; nt++) {
        int c = nw * 120 + nt * 8 + 2 * (lane & 3);
        float b0 = biasB[c], b1 = biasB[c + 1];
        #pragma unroll
        for (int mt = 0; mt < 2; mt++) {
            #pragma unroll
            for (int rh = 0; rh < 2; rh++) {
                int t = t0 + mw * 32 + mt * 16 + (lane >> 2) + rh * 8;
                size_t gi = ((size_t)b * TLEN + t) * 240 + c;
                float2 v;
                v.x = sk[mt][nt][rh * 2 + 0] + b0;
                v.y = sk[mt][nt][rh * 2 + 1] + b1;
                if (!first) {
                    float2 o = *(float2*)(g_skip + gi);
                    v.x += o.x; v.y += o.y;
                }
                *(float2*)(g_skip + gi) = v;
            }
        }
    }

    // ========== phase 2b: res[128t x 120c], K=120 ==========
    {
        float rs[2][8][4];
        #pragma unroll
        for (int mt = 0; mt < 2; mt++)
            #pragma unroll
            for (int nt = 0; nt < 8; nt++)
                #pragma unroll
                for (int e = 0; e < 4; e++) rs[mt][nt][e] = 0.f;
        const int NT = 8 - nw;

        for (int q2 = 0; q2 < 2; q2++) {
            if (q2 == 0) { stage2r(1); cpa_wait<1>(); }
            else         { cpa_wait<0>(); }
            __syncthreads();
            uint32_t xb  = smb + XBUF(q2);
            uint32_t wbh = smb + WBUF(q2);
            uint32_t wbl = wbh + 30720;
            #pragma unroll
            for (int kt = 0; kt < 4; kt++) {
                uint32_t ah[2][4], al[2][4];
                #pragma unroll
                for (int mt = 0; mt < 2; mt++) {
                    int ar = mw * 32 + mt * 16 + (lane & 15);
                    int ack = kt * 2 + (lane >> 4);
                    uint32_t ab = ar * 128 + (((uint32_t)(ack ^ (ar & 7))) << 4);
                    ldsm_x4(ah[mt], xb + ab);
                    ldsm_x4(al[mt], xb + 16384 + ab);
                }
                int bn2 = nw * 64 + (lane & 7);
                int bck = kt * 2 + bsel;
                #pragma unroll
                for (int nt = 0; nt < 8; nt++) {
                    if (nt < NT) {
                        int n = bn2 + nt * 8;
                        uint32_t bb = n * 128 + (((uint32_t)(bck ^ (n & 7))) << 4);
                        uint32_t bh2[2], bl2[2];
                        ldsm_x2(bh2, wbh + bb);
                        ldsm_x2(bl2, wbl + bb);
                        #pragma unroll
                        for (int mt = 0; mt < 2; mt++) {
                            mma16816(rs[mt][nt], ah[mt], bh2[0], bh2[1]);
                            mma16816(rs[mt][nt], ah[mt], bl2[0], bl2[1]);
                            mma16816(rs[mt][nt], al[mt], bh2[0], bh2[1]);
                        }
                    }
                }
            }
            __syncthreads();
        }

        // res epilogue
        const uint32_t* rInH = (const uint32_t*)resInH;
        const uint32_t* rInL = (const uint32_t*)resInL;
        uint32_t* rOutH = (uint32_t*)resOutH;
        uint32_t* rOutL = (uint32_t*)resOutL;
        #pragma unroll
        for (int nt = 0; nt < 8; nt++) {
            if (nt < NT) {
                int c = nw * 64 + nt * 8 + 2 * (lane & 3);
                float b0 = biasB[240 + c], b1 = biasB[240 + c + 1];
                #pragma unroll
                for (int mt = 0; mt < 2; mt++) {
                    #pragma unroll
                    for (int rh = 0; rh < 2; rh++) {
                        int t = t0 + mw * 32 + mt * 16 + (lane >> 2) + rh * 8;
                        size_t ri = ((size_t)b * TLEN + t) * 64 + (c >> 1);
                        U1B vh, vl, oh, ol;
                        vh.u = rInH[ri]; vl.u = rInL[ri];
                        float o0 = rs[mt][nt][rh * 2 + 0] + b0
                                 + __bfloat162float(vh.h[0]) + __bfloat162float(vl.h[0]);
                        float o1 = rs[mt][nt][rh * 2 + 1] + b1
                                 + __bfloat162float(vh.h[1]) + __bfloat162float(vl.h[1]);
                        split_bf16(o0, oh.h[0], ol.h[0]);
                        split_bf16(o1, oh.h[1], ol.h[1]);
                        rOutH[ri] = oh.u;
                        rOutL[ri] = ol.u;
                    }
                }
            }
        }
    }
    // zero pad channels 120-127 of resOut
    if (tid < 128) {
        size_t rp = ((size_t)b * TLEN + t0 + tid) * 16 + 15;
        resOutH[rp] = make_uint4(0, 0, 0, 0);
        resOutL[rp] = make_uint4(0, 0, 0, 0);
    }
}

// ---------------- fused mma head kernel (unchanged from R9) ---------------
#define HOFF_OB   0
#define HOFF_EB   1024
#define HOFF_A1H  2048
#define HOFF_A1L  18432
#define HOFF_WHH  34816
#define HOFF_WHL  67584
#define HOFF_A2H  100352
#define HOFF_A2L  165888
#define SMEM_HEAD 231424

__global__ void __launch_bounds__(256, 1) head_mma(
    const float* __restrict__ out_b, const float* __restrict__ end_b,
    float* __restrict__ out)
{
    extern __shared__ __align__(16) char sm[];
    const uint32_t smb = smem_u32(sm);
    const int tid  = threadIdx.x;
    const int lane = tid & 31;
    const int wid  = tid >> 5;
    const int mw   = wid >> 1;
    const int nw   = wid & 1;
    const int b    = blockIdx.y;
    const int t0   = blockIdx.x * 128;

    float* obs = (float*)(sm + HOFF_OB);
    float* ebs = (float*)(sm + HOFF_EB);
    for (int e = tid; e < 256; e += 256) { obs[e] = out_b[e]; ebs[e] = end_b[e]; }

    float ac[2][16][4];
    #pragma unroll
    for (int mt = 0; mt < 2; mt++)
        #pragma unroll
        for (int nt = 0; nt < 16; nt++)
            #pragma unroll
            for (int e = 0; e < 4; e++) ac[mt][nt][e] = 0.f;

    for (int q = 0; q < 4; q++) {
        __syncthreads();
        for (int e = tid; e < 1024; e += 256) {
            int r = e >> 3, ii = e & 7;
            int c0 = q * 64 + ii * 8;
            U4B uh, ul;
            if (c0 < 240) {
                size_t gi = ((size_t)b * TLEN + t0 + r) * 240 + c0;
                float4 v0 = *(const float4*)(g_skip + gi);
                float4 v1 = *(const float4*)(g_skip + gi + 4);
                float vv[8] = {v0.x, v0.y, v0.z, v0.w, v1.x, v1.y, v1.z, v1.w};
                #pragma unroll
                for (int k = 0; k < 8; k++)
                    split_bf16(fmaxf(vv[k], 0.f), uh.h[k], ul.h[k]);
            } else {
                uh.u = make_uint4(0,0,0,0); ul.u = make_uint4(0,0,0,0);
            }
            uint32_t byte = sw128((r << 7) + (ii << 4));
            *(uint4*)(sm + HOFF_A1H + byte) = uh.u;
            *(uint4*)(sm + HOFF_A1L + byte) = ul.u;
        }
        for (int e = tid; e < 2048; e += 256) {
            ((uint4*)(sm + HOFF_WHH))[e] = g_Woh[q * 2048 + e];
            ((uint4*)(sm + HOFF_WHL))[e] = g_Wol[q * 2048 + e];
        }
        __syncthreads();
        #pragma unroll
        for (int kt = 0; kt < 4; kt++) {
            uint32_t ah[2][4], al[2][4];
            #pragma unroll
            for (int mt = 0; mt < 2; mt++) {
                int ar = mw * 32 + mt * 16 + (lane & 15);
                int ack = kt * 2 + (lane >> 4);
                uint32_t ab = ar * 128 + (((uint32_t)(ack ^ (ar & 7))) << 4);
                ldsm_x4(ah[mt], smb + HOFF_A1H + ab);
                ldsm_x4(al[mt], smb + HOFF_A1L + ab);
            }
            int bn = nw * 128 + (lane & 7);
            int bsel = (lane >> 3) & 1;
            #pragma unroll
            for (int nt = 0; nt < 16; nt++) {
                int n = bn + nt * 8;
                int bck = kt * 2 + bsel;
                uint32_t bb = n * 128 + (((uint32_t)(bck ^ (n & 7))) << 4);
                uint32_t bh[2], bl[2];
                ldsm_x2(bh, smb + HOFF_WHH + bb);
                ldsm_x2(bl, smb + HOFF_WHL + bb);
                #pragma unroll
                for (int mt = 0; mt < 2; mt++) {
                    mma16816(ac[mt][nt], ah[mt], bh[0], bh[1]);
                    mma16816(ac[mt][nt], ah[mt], bl[0], bl[1]);
                    mma16816(ac[mt][nt], al[mt], bh[0], bh[1]);
                }
            }
        }
    }

    __syncthreads();
    #pragma unroll
    for (int nt = 0; nt < 16; nt++) {
        int p = nw * 128 + nt * 8 + 2 * (lane & 3);
        int chunk = p >> 6;
        int p2 = p & 63;
        float b0 = obs[p], b1 = obs[p + 1];
        #pragma unroll
        for (int mt = 0; mt < 2; mt++) {
            #pragma unroll
            for (int rh = 0; rh < 2; rh++) {
                int r = mw * 32 + mt * 16 + (lane >> 2) + rh * 8;
                float v0 = fmaxf(ac[mt][nt][rh * 2 + 0] + b0, 0.f);
                float v1 = fmaxf(ac[mt][nt][rh * 2 + 1] + b1, 0.f);
                U1B ph, pl;
                split_bf16(v0, ph.h[0], pl.h[0]);
                split_bf16(v1, ph.h[1], pl.h[1]);
                uint32_t byte = r * 128 + (((uint32_t)((p2 >> 3) ^ (r & 7))) << 4)
                              + (p2 & 7) * 2;
                *(uint32_t*)(sm + HOFF_A2H + chunk * 16384 + byte) = ph.u;
                *(uint32_t*)(sm + HOFF_A2L + chunk * 16384 + byte) = pl.u;
            }
        }
    }

    #pragma unroll
    for (int mt = 0; mt < 2; mt++)
        #pragma unroll
        for (int nt = 0; nt < 16; nt++)
            #pragma unroll
            for (int e = 0; e < 4; e++) ac[mt][nt][e] = 0.f;

    for (int q = 0; q < 4; q++) {
        __syncthreads();
        for (int e = tid; e < 2048; e += 256) {
            ((uint4*)(sm + HOFF_WHH))[e] = g_Weh[q * 2048 + e];
            ((uint4*)(sm + HOFF_WHL))[e] = g_Wel[q * 2048 + e];
        }
        __syncthreads();
        #pragma unroll
        for (int kt = 0; kt < 4; kt++) {
            uint32_t ah[2][4], al[2][4];
            #pragma unroll
            for (int mt = 0; mt < 2; mt++) {
                int ar = mw * 32 + mt * 16 + (lane & 15);
                int ack = kt * 2 + (lane >> 4);
                uint32_t ab = ar * 128 + (((uint32_t)(ack ^ (ar & 7))) << 4);
                ldsm_x4(ah[mt], smb + HOFF_A2H + q * 16384 + ab);
                ldsm_x4(al[mt], smb + HOFF_A2L + q * 16384 + ab);
            }
            int bn = nw * 128 + (lane & 7);
            int bsel = (lane >> 3) & 1;
            #pragma unroll
            for (int nt = 0; nt < 16; nt++) {
                int n = bn + nt * 8;
                int bck = kt * 2 + bsel;
                uint32_t bb = n * 128 + (((uint32_t)(bck ^ (n & 7))) << 4);
                uint32_t bh[2], bl[2];
                ldsm_x2(bh, smb + HOFF_WHH + bb);
                ldsm_x2(bl, smb + HOFF_WHL + bb);
                #pragma unroll
                for (int mt = 0; mt < 2; mt++) {
                    mma16816(ac[mt][nt], ah[mt], bh[0], bh[1]);
                    mma16816(ac[mt][nt], ah[mt], bl[0], bl[1]);
                    mma16816(ac[mt][nt], al[mt], bh[0], bh[1]);
                }
            }
        }
    }

    #pragma unroll
    for (int nt = 0; nt < 16; nt++) {
        int o0 = nw * 128 + nt * 8 + 2 * (lane & 3);
        float b0 = ebs[o0], b1 = ebs[o0 + 1];
        #pragma unroll
        for (int mt = 0; mt < 2; mt++) {
            #pragma unroll
            for (int rh = 0; rh < 2; rh++) {
                int t = t0 + mw * 32 + mt * 16 + (lane >> 2) + rh * 8;
                out[((size_t)b * NC + o0) * TLEN + t]     = ac[mt][nt][rh * 2 + 0] + b0;
                out[((size_t)b * NC + o0 + 1) * TLEN + t] = ac[mt][nt][rh * 2 + 1] + b1;
            }
        }
    }
}

// ---------------- host launcher -------------------------------------------
extern "C" void kernel_launch(void* const* d_in, const int* in_sizes, int n_in,
                              void* d_out, int out_size) {
    const float* wav    = (const float*)d_in[0];
    const float* cond   = (const float*)d_in[1];
    const float* wav_w  = (const float*)d_in[2];
    const float* wav_b  = (const float*)d_in[3];
    const float* cond_w = (const float*)d_in[4];
    const float* cond_b = (const float*)d_in[5];
    const float* dil_w  = (const float*)d_in[6];
    const float* dil_b  = (const float*)d_in[7];
    const float* skip_w = (const float*)d_in[8];
    const float* skip_b = (const float*)d_in[9];
    const float* res_w  = (const float*)d_in[10];
    const float* res_b  = (const float*)d_in[11];
    const float* out_w  = (const float*)d_in[12];
    const float* out_b  = (const float*)d_in[13];
    const float* end_w  = (const float*)d_in[14];
    const float* end_b  = (const float*)d_in[15];

    cudaFuncSetAttribute(block_mma, cudaFuncAttributeMaxDynamicSharedMemorySize,
                         SMEM_MMA);
    cudaFuncSetAttribute(head_mma, cudaFuncAttributeMaxDynamicSharedMemorySize,
                         SMEM_HEAD);

    repack_w1<<<(NBLK * 6 * 240 * 64 + 255) / 256, 256>>>(dil_w, cond_w);
    repack_w2<<<(NBLK * 2 * (240 + 120) * 64 + 255) / 256, 256>>>(skip_w, res_w);
    repack_whead<<<(2 * 4 * 256 * 64 + 255) / 256, 256>>>(out_w, end_w);
    prologue_res<<<(BB * TLEN * 16 + 255) / 256, 256>>>(wav, wav_w, wav_b);
    prologue_cond<<<(BB * TLEN * 16 + 255) / 256, 256>>>(cond);

    dim3 gridB(TLEN / 128, BB);
    for (int i = 0; i < NBLK; i++) {
        int d = 1 << (i % 8);
        block_mma<<<gridB, 256, SMEM_MMA>>>(dil_b, cond_b, skip_b, res_b,
                                            i, d, (i == 0) ? 1 : 0, i & 1);
    }
    head_mma<<<gridB, 256, SMEM_HEAD>>>(out_b, end_b, (float*)d_out);
}

// round 11
// speedup vs baseline: 1.5381x; 1.0438x over previous
#include <cuda_runtime.h>
#include <cuda_bf16.h>
#include <math.h>
#include <stdint.h>

#define BB   4
#define TLEN 32768
#define NM   80
#define RC   120
#define SC   240
#define NBLK 16
#define NC   256

// ---------------- device scratch (no allocations allowed) ----------------
__device__ uint4 g_resAH[BB * TLEN * 16];
__device__ uint4 g_resAL[BB * TLEN * 16];
__device__ uint4 g_resBH[BB * TLEN * 16];
__device__ uint4 g_resBL[BB * TLEN * 16];
__device__ uint4 g_condH[BB * TLEN * 16];
__device__ uint4 g_condL[BB * TLEN * 16];
__device__ float g_skip [BB * TLEN * SC];   // [b][t][c]
__device__ uint4 g_W1h[NBLK * 5 * 1920];    // phase1, K packed to 320 (5 chunks)
__device__ uint4 g_W1l[NBLK * 5 * 1920];
__device__ uint4 g_W2sh[NBLK * 2 * 1920];   // skip [240][64]
__device__ uint4 g_W2sl[NBLK * 2 * 1920];
__device__ uint4 g_W2rh[NBLK * 2 * 960];    // res  [120][64]
__device__ uint4 g_W2rl[NBLK * 2 * 960];
__device__ uint4 g_Woh[4 * 2048];           // out_w [256][64] chunks, swizzled
__device__ uint4 g_Wol[4 * 2048];
__device__ uint4 g_Weh[4 * 2048];           // end_w [256][64] chunks, swizzled
__device__ uint4 g_Wel[4 * 2048];

// ---------------- helpers -------------------------------------------------
__device__ __forceinline__ uint32_t smem_u32(const void* p) {
    uint32_t a;
    asm("{ .reg .u64 t; cvta.to.shared.u64 t, %1; cvt.u32.u64 %0, t; }"
        : "=r"(a) : "l"(p));
    return a;
}
__device__ __forceinline__ uint32_t sw128(uint32_t b) { return b ^ ((b >> 3) & 0x70); }

union U4B { uint4 u; __nv_bfloat16 h[8]; };
union U1B { uint32_t u; __nv_bfloat16 h[2]; };

__device__ __forceinline__ void split_bf16(float x, __nv_bfloat16& hi, __nv_bfloat16& lo) {
    hi = __float2bfloat16(x);
    lo = __float2bfloat16(x - __bfloat162float(hi));
}
__device__ __forceinline__ float fast_tanh(float x) {
    return 1.f - 2.f / (1.f + __expf(2.f * x));
}
__device__ __forceinline__ float fast_sigmoid(float x) {
    return 1.f / (1.f + __expf(-x));
}

__device__ __forceinline__ void ldsm_x4(uint32_t* r, uint32_t addr) {
    asm volatile("ldmatrix.sync.aligned.m8n8.x4.shared.b16 {%0,%1,%2,%3}, [%4];"
                 : "=r"(r[0]), "=r"(r[1]), "=r"(r[2]), "=r"(r[3]) : "r"(addr));
}
__device__ __forceinline__ void ldsm_x2(uint32_t* r, uint32_t addr) {
    asm volatile("ldmatrix.sync.aligned.m8n8.x2.shared.b16 {%0,%1}, [%2];"
                 : "=r"(r[0]), "=r"(r[1]) : "r"(addr));
}
__device__ __forceinline__ void mma16816(float* c, const uint32_t* a,
                                         uint32_t b0, uint32_t b1) {
    asm("mma.sync.aligned.m16n8k16.row.col.f32.bf16.bf16.f32 "
        "{%0,%1,%2,%3}, {%4,%5,%6,%7}, {%8,%9}, {%0,%1,%2,%3};"
        : "+f"(c[0]), "+f"(c[1]), "+f"(c[2]), "+f"(c[3])
        : "r"(a[0]), "r"(a[1]), "r"(a[2]), "r"(a[3]), "r"(b0), "r"(b1));
}
__device__ __forceinline__ void cpa16(uint32_t smem, const void* gmem, uint32_t ssz) {
    asm volatile("cp.async.cg.shared.global [%0], [%1], 16, %2;"
                 :: "r"(smem), "l"(gmem), "r"(ssz) : "memory");
}
#define CPA_COMMIT() asm volatile("cp.async.commit_group;" ::: "memory")
template <int N> __device__ __forceinline__ void cpa_wait() {
    asm volatile("cp.async.wait_group %0;" :: "n"(N) : "memory");
}

// ---------------- weight repack kernels -----------------------------------
// phase1 K packed: k 0..119 = dil tap0, 120..239 = dil tap1, 240..319 = cond
__global__ void repack_w1(const float* __restrict__ dil_w,
                          const float* __restrict__ cond_w) {
    int idx = blockIdx.x * blockDim.x + threadIdx.x;
    const int total = NBLK * 5 * 240 * 64;
    if (idx >= total) return;
    int kk = idx & 63;
    int n  = (idx >> 6) % 240;
    int q  = (idx / (64 * 240)) % 5;
    int i  = idx / (64 * 240 * 5);
    int c  = (n >> 1) + (n & 1) * 120;          // original output channel
    int kpos = q * 64 + kk;                     // 0..319, no padding
    float w;
    if (kpos < 120)      w = dil_w[((i*240 + c)*120 + kpos)*2 + 0];
    else if (kpos < 240) w = dil_w[((i*240 + c)*120 + (kpos - 120))*2 + 1];
    else                 w = cond_w[(i*240 + c)*80 + (kpos - 240)];
    __nv_bfloat16 hi, lo; split_bf16(w, hi, lo);
    int elem = sw128(n * 128 + kk * 2) >> 1;
    size_t base = (size_t)(i * 5 + q) * 15360;
    ((__nv_bfloat16*)g_W1h)[base + elem] = hi;
    ((__nv_bfloat16*)g_W1l)[base + elem] = lo;
}

__global__ void repack_w2(const float* __restrict__ skip_w,
                          const float* __restrict__ res_w) {
    int idx = blockIdx.x * blockDim.x + threadIdx.x;
    const int totS = NBLK * 2 * 240 * 64;
    const int totR = NBLK * 2 * 120 * 64;
    if (idx < totS) {
        int kk = idx & 63;
        int c  = (idx >> 6) % 240;
        int q  = (idx / (64 * 240)) % 2;
        int i  = idx / (64 * 240 * 2);
        int k  = q * 64 + kk;
        float w = (k < 120) ? skip_w[(i*240 + c)*120 + k] : 0.f;
        __nv_bfloat16 hi, lo; split_bf16(w, hi, lo);
        int elem = sw128(c * 128 + kk * 2) >> 1;
        size_t base = (size_t)(i * 2 + q) * 15360;
        ((__nv_bfloat16*)g_W2sh)[base + elem] = hi;
        ((__nv_bfloat16*)g_W2sl)[base + elem] = lo;
    } else if (idx < totS + totR) {
        int j = idx - totS;
        int kk = j & 63;
        int c  = (j >> 6) % 120;
        int q  = (j / (64 * 120)) % 2;
        int i  = j / (64 * 120 * 2);
        int k  = q * 64 + kk;
        float w = (k < 120) ? res_w[(i*120 + c)*120 + k] : 0.f;
        __nv_bfloat16 hi, lo; split_bf16(w, hi, lo);
        int elem = sw128(c * 128 + kk * 2) >> 1;
        size_t base = (size_t)(i * 2 + q) * 7680;
        ((__nv_bfloat16*)g_W2rh)[base + elem] = hi;
        ((__nv_bfloat16*)g_W2rl)[base + elem] = lo;
    }
}

// head weights: [256 o][64 k] chunks q=0..3, swizzled rows of 128B
__global__ void repack_whead(const float* __restrict__ out_w,
                             const float* __restrict__ end_w) {
    int idx = blockIdx.x * blockDim.x + threadIdx.x;
    const int half = 4 * 256 * 64;
    if (idx >= 2 * half) return;
    int sel = idx / half;
    int j = idx % half;
    int kk = j & 63;
    int n  = (j >> 6) % 256;
    int q  = j / (64 * 256);
    int k  = q * 64 + kk;
    float w;
    if (sel == 0) w = (k < 240) ? out_w[n * 240 + k] : 0.f;
    else          w = end_w[n * 256 + k];
    __nv_bfloat16 hi, lo; split_bf16(w, hi, lo);
    int elem = sw128(n * 128 + kk * 2) >> 1;
    size_t base = (size_t)q * 16384;
    if (sel == 0) {
        ((__nv_bfloat16*)g_Woh)[base + elem] = hi;
        ((__nv_bfloat16*)g_Wol)[base + elem] = lo;
    } else {
        ((__nv_bfloat16*)g_Weh)[base + elem] = hi;
        ((__nv_bfloat16*)g_Wel)[base + elem] = lo;
    }
}

// ---------------- prologues -----------------------------------------------
__global__ void prologue_res(const float* __restrict__ wav,
                             const float* __restrict__ wav_w,
                             const float* __restrict__ wav_b) {
    int idx = blockIdx.x * blockDim.x + threadIdx.x;
    const int total = BB * TLEN * 16;
    if (idx >= total) return;
    int chunk = idx & 15;
    int t = (idx >> 4) % TLEN;
    int b = idx / (TLEN * 16);
    float wv = wav[(size_t)b * TLEN + t];
    U4B uh, ul;
    #pragma unroll
    for (int e = 0; e < 8; e++) {
        int c = chunk * 8 + e;
        float v = (c < RC) ? (wav_w[c] * wv + wav_b[c]) : 0.f;
        split_bf16(v, uh.h[e], ul.h[e]);
    }
    g_resAH[idx] = uh.u;
    g_resAL[idx] = ul.u;
}

__global__ void prologue_cond(const float* __restrict__ cond) {
    int idx = blockIdx.x * blockDim.x + threadIdx.x;
    const int total = BB * TLEN * 16;
    if (idx >= total) return;
    int chunk = idx & 15;
    int t = (idx >> 4) % TLEN;
    int b = idx / (TLEN * 16);
    U4B uh, ul;
    #pragma unroll
    for (int e = 0; e < 8; e++) {
        int c = chunk * 8 + e;
        float v = (c < NM) ? cond[((size_t)b * NM + c) * TLEN + t] : 0.f;
        split_bf16(v, uh.h[e], ul.h[e]);
    }
    g_condH[idx] = uh.u;
    g_condL[idx] = ul.u;
}

// ---------------- mma per-layer kernel (cp.async pipelined, K=320) --------
#define OFF_BA   0
#define OFF_BB   1024
#define OFF_X    4096
#define XBUF(i)  (OFF_X + (i) * 32768)          // XH at +0, XL at +16384
#define OFF_W    69632
#define WBUF(i)  (OFF_W + (i) * 61440)          // H at +0, L at +30720
#define SMEM_MMA 192512

__global__ void __launch_bounds__(256, 1) block_mma(
    const float* __restrict__ dil_b, const float* __restrict__ cond_b,
    const float* __restrict__ skip_b, const float* __restrict__ res_b,
    int layer, int d, int first, int swap)
{
    extern __shared__ __align__(16) char sm[];
    const uint32_t smb = smem_u32(sm);
    const int tid  = threadIdx.x;
    const int lane = tid & 31;
    const int wid  = tid >> 5;
    const int mw   = wid >> 1;            // 0..3 (m)
    const int nw   = wid & 1;             // 0..1 (n)
    const int b    = blockIdx.y;
    const int t0   = blockIdx.x * 128;

    const uint4* resInH = swap ? g_resBH : g_resAH;
    const uint4* resInL = swap ? g_resBL : g_resAL;
    uint4* resOutH = swap ? g_resAH : g_resBH;
    uint4* resOutL = swap ? g_resAL : g_resBL;

    // ---- staging helpers ----
    auto stage1 = [&](int q) {    // K-packed: kg<15 shift-res | <30 res | cond
        uint32_t xb = smb + XBUF(q & 1);
        for (int e = tid; e < 1024; e += 256) {
            int r = e >> 3, ii = e & 7;
            int kg = q * 8 + ii;
            const uint4* sH; const uint4* sL; int t; int grp;
            if (kg < 15)      { sH = resInH;  sL = resInL;  t = t0 - d + r; grp = kg; }
            else if (kg < 30) { sH = resInH;  sL = resInL;  t = t0 + r;     grp = kg - 15; }
            else              { sH = g_condH; sL = g_condL; t = t0 + r;     grp = kg - 30; }
            uint32_t ok = (t >= 0) ? 16u : 0u;
            int tc = (t >= 0) ? t : 0;
            size_t si = ((size_t)b * TLEN + tc) * 16 + grp;
            uint32_t byte = sw128((r << 7) + (ii << 4));
            cpa16(xb + byte,          sH + si, ok);
            cpa16(xb + 16384 + byte,  sL + si, ok);
        }
        uint32_t wb = smb + WBUF(q & 1);
        size_t wgb = (size_t)(layer * 5 + q) * 1920;
        for (int e = tid; e < 1920; e += 256) {
            cpa16(wb + e * 16,          g_W1h + wgb + e, 16);
            cpa16(wb + 30720 + e * 16,  g_W1l + wgb + e, 16);
        }
        CPA_COMMIT();
    };
    auto stage2s = [&](int chunk, int buf) {
        uint32_t wb = smb + WBUF(buf);
        size_t bs = (size_t)(layer * 2 + chunk) * 1920;
        for (int e = tid; e < 1920; e += 256) {
            cpa16(wb + e * 16,          g_W2sh + bs + e, 16);
            cpa16(wb + 30720 + e * 16,  g_W2sl + bs + e, 16);
        }
        CPA_COMMIT();
    };
    auto stage2r = [&](int chunk, int buf) {
        uint32_t wb = smb + WBUF(buf);
        size_t br = (size_t)(layer * 2 + chunk) * 960;
        for (int e = tid; e < 960; e += 256) {
            cpa16(wb + e * 16,          g_W2rh + br + e, 16);
            cpa16(wb + 30720 + e * 16,  g_W2rl + br + e, 16);
        }
        CPA_COMMIT();
    };

    stage1(0);

    float* biasA = (float*)(sm + OFF_BA);
    float* biasB = (float*)(sm + OFF_BB);
    for (int e = tid; e < 240; e += 256)
        biasA[e] = dil_b[layer * 240 + e] + cond_b[layer * 240 + e];
    for (int e = tid; e < 360; e += 256)
        biasB[e] = (e < 240) ? skip_b[layer * 240 + e] : res_b[layer * 120 + e - 240];

    // ========== phase 1: g[128t x 240n(permuted)], K=320 (5 chunks) =======
    float ac[2][15][4];
    #pragma unroll
    for (int mt = 0; mt < 2; mt++)
        #pragma unroll
        for (int nt = 0; nt < 15; nt++)
            #pragma unroll
            for (int e = 0; e < 4; e++) ac[mt][nt][e] = 0.f;

    const int bn   = nw * 120 + (lane & 7);
    const int bhi  = (lane >> 4) << 3;         // pairing: lanes 16-31 -> +8 rows
    const int bsel = (lane >> 3) & 1;

    for (int q = 0; q < 5; q++) {
        if (q < 4) stage1(q + 1);
        else       stage2s(0, 1);              // q=4 reads buf0 -> prefetch to buf1
        cpa_wait<1>();
        __syncthreads();
        uint32_t xb  = smb + XBUF(q & 1);
        uint32_t wbh = smb + WBUF(q & 1);
        uint32_t wbl = wbh + 30720;
        #pragma unroll
        for (int kt = 0; kt < 4; kt++) {
            uint32_t ah[2][4], al[2][4];
            #pragma unroll
            for (int mt = 0; mt < 2; mt++) {
                int ar = mw * 32 + mt * 16 + (lane & 15);
                int ack = kt * 2 + (lane >> 4);
                uint32_t ab = ar * 128 + (((uint32_t)(ack ^ (ar & 7))) << 4);
                ldsm_x4(ah[mt], xb + ab);
                ldsm_x4(al[mt], xb + 16384 + ab);
            }
            int bck = kt * 2 + bsel;
            #pragma unroll
            for (int j = 0; j < 7; j++) {
                int n0 = bn + j * 16 + bhi;
                uint32_t bb = n0 * 128 + (((uint32_t)(bck ^ (n0 & 7))) << 4);
                uint32_t bq[4], bl4[4];
                ldsm_x4(bq,  wbh + bb);
                ldsm_x4(bl4, wbl + bb);
                #pragma unroll
                for (int mt = 0; mt < 2; mt++) {
                    mma16816(ac[mt][2*j],   ah[mt], bq[0],  bq[1]);
                    mma16816(ac[mt][2*j],   ah[mt], bl4[0], bl4[1]);
                    mma16816(ac[mt][2*j],   al[mt], bq[0],  bq[1]);
                    mma16816(ac[mt][2*j+1], ah[mt], bq[2],  bq[3]);
                    mma16816(ac[mt][2*j+1], ah[mt], bl4[2], bl4[3]);
                    mma16816(ac[mt][2*j+1], al[mt], bq[2],  bq[3]);
                }
            }
            {   // nt = 14
                int n = nw * 120 + 112 + (lane & 7);
                uint32_t bb = n * 128 + (((uint32_t)(bck ^ (n & 7))) << 4);
                uint32_t bh2[2], bl2[2];
                ldsm_x2(bh2, wbh + bb);
                ldsm_x2(bl2, wbl + bb);
                #pragma unroll
                for (int mt = 0; mt < 2; mt++) {
                    mma16816(ac[mt][14], ah[mt], bh2[0], bh2[1]);
                    mma16816(ac[mt][14], ah[mt], bl2[0], bl2[1]);
                    mma16816(ac[mt][14], al[mt], bh2[0], bh2[1]);
                }
            }
        }
        __syncthreads();
    }

    // ========== gating (registers) -> A2 tile in X buffers ==========
    #pragma unroll
    for (int nt = 0; nt < 15; nt++) {
        int p = nw * 60 + nt * 4 + (lane & 3);
        int reg = (p < 64) ? 0 : 1;
        int p2 = p & 63;
        float ba_t = biasA[p];
        float ba_s = biasA[p + 120];
        #pragma unroll
        for (int mt = 0; mt < 2; mt++) {
            #pragma unroll
            for (int rh = 0; rh < 2; rh++) {
                int r = mw * 32 + mt * 16 + (lane >> 2) + rh * 8;
                float gt = ac[mt][nt][rh * 2 + 0] + ba_t;
                float gs = ac[mt][nt][rh * 2 + 1] + ba_s;
                float v = fast_tanh(gt) * fast_sigmoid(gs);
                __nv_bfloat16 hi, lo; split_bf16(v, hi, lo);
                uint32_t byte = r * 128 + (((uint32_t)((p2 >> 3) ^ (r & 7))) << 4)
                              + (p2 & 7) * 2;
                *(__nv_bfloat16*)(sm + XBUF(reg) + byte) = hi;
                *(__nv_bfloat16*)(sm + XBUF(reg) + 16384 + byte) = lo;
            }
        }
    }
    // zero-pad A2 chunk1 (p 120..127)
    if (tid < 128) {
        uint32_t byte = tid * 128 + ((7u ^ (tid & 7)) << 4);
        *(uint4*)(sm + XBUF(1) + byte)          = make_uint4(0, 0, 0, 0);
        *(uint4*)(sm + XBUF(1) + 16384 + byte)  = make_uint4(0, 0, 0, 0);
    }

    // ========== phase 2a: skip[128t x 240c], K=120 ==========
    float sk[2][15][4];
    #pragma unroll
    for (int mt = 0; mt < 2; mt++)
        #pragma unroll
        for (int nt = 0; nt < 15; nt++)
            #pragma unroll
            for (int e = 0; e < 4; e++) sk[mt][nt][e] = 0.f;

    for (int q2 = 0; q2 < 2; q2++) {
        if (q2 == 0) stage2s(1, 0);
        else         stage2r(0, 1);
        cpa_wait<1>();
        __syncthreads();
        uint32_t xb  = smb + XBUF(q2);
        uint32_t wbh = smb + WBUF(1 - q2);
        uint32_t wbl = wbh + 30720;
        #pragma unroll
        for (int kt = 0; kt < 4; kt++) {
            uint32_t ah[2][4], al[2][4];
            #pragma unroll
            for (int mt = 0; mt < 2; mt++) {
                int ar = mw * 32 + mt * 16 + (lane & 15);
                int ack = kt * 2 + (lane >> 4);
                uint32_t ab = ar * 128 + (((uint32_t)(ack ^ (ar & 7))) << 4);
                ldsm_x4(ah[mt], xb + ab);
                ldsm_x4(al[mt], xb + 16384 + ab);
            }
            int bck = kt * 2 + bsel;
            #pragma unroll
            for (int j = 0; j < 7; j++) {
                int n0 = bn + j * 16 + bhi;
                uint32_t bb = n0 * 128 + (((uint32_t)(bck ^ (n0 & 7))) << 4);
                uint32_t bq[4], bl4[4];
                ldsm_x4(bq,  wbh + bb);
                ldsm_x4(bl4, wbl + bb);
                #pragma unroll
                for (int mt = 0; mt < 2; mt++) {
                    mma16816(sk[mt][2*j],   ah[mt], bq[0],  bq[1]);
                    mma16816(sk[mt][2*j],   ah[mt], bl4[0], bl4[1]);
                    mma16816(sk[mt][2*j],   al[mt], bq[0],  bq[1]);
                    mma16816(sk[mt][2*j+1], ah[mt], bq[2],  bq[3]);
                    mma16816(sk[mt][2*j+1], ah[mt], bl4[2], bl4[3]);
                    mma16816(sk[mt][2*j+1], al[mt], bq[2],  bq[3]);
                }
            }
            {
                int n = nw * 120 + 112 + (lane & 7);
                uint32_t bb = n * 128 + (((uint32_t)(bck ^ (n & 7))) << 4);
                uint32_t bh2[2], bl2[2];
                ldsm_x2(bh2, wbh + bb);
                ldsm_x2(bl2, wbl + bb);
                #pragma unroll
                for (int mt = 0; mt < 2; mt++) {
                    mma16816(sk[mt][14], ah[mt], bh2[0], bh2[1]);
                    mma16816(sk[mt][14], ah[mt], bl2[0], bl2[1]);
                    mma16816(sk[mt][14], al[mt], bh2[0], bh2[1]);
                }
            }
        }
        __syncthreads();
    }

    // skip epilogue: [b][t][240] fp32 accumulate
    #pragma unroll
    for (int nt = 0; nt < 15; nt++) {
        int c = nw * 120 + nt * 8 + 2 * (lane & 3);
        float b0 = biasB[c], b1 = biasB[c + 1];
        #pragma unroll
        for (int mt = 0; mt < 2; mt++) {
            #pragma unroll
            for (int rh = 0; rh < 2; rh++) {
                int t = t0 + mw * 32 + mt * 16 + (lane >> 2) + rh * 8;
                size_t gi = ((size_t)b * TLEN + t) * 240 + c;
                float2 v;
                v.x = sk[mt][nt][rh * 2 + 0] + b0;
                v.y = sk[mt][nt][rh * 2 + 1] + b1;
                if (!first) {
                    float2 o = *(float2*)(g_skip + gi);
                    v.x += o.x; v.y += o.y;
                }
                *(float2*)(g_skip + gi) = v;
            }
        }
    }

    // ========== phase 2b: res[128t x 120c], K=120 ==========
    {
        float rs[2][8][4];
        #pragma unroll
        for (int mt = 0; mt < 2; mt++)
            #pragma unroll
            for (int nt = 0; nt < 8; nt++)
                #pragma unroll
                for (int e = 0; e < 4; e++) rs[mt][nt][e] = 0.f;
        const int NT = 8 - nw;

        for (int q2 = 0; q2 < 2; q2++) {
            if (q2 == 0) { stage2r(1, 0); cpa_wait<1>(); }
            else         { cpa_wait<0>(); }
            __syncthreads();
            uint32_t xb  = smb + XBUF(q2);
            uint32_t wbh = smb + WBUF(1 - q2);
            uint32_t wbl = wbh + 30720;
            #pragma unroll
            for (int kt = 0; kt < 4; kt++) {
                uint32_t ah[2][4], al[2][4];
                #pragma unroll
                for (int mt = 0; mt < 2; mt++) {
                    int ar = mw * 32 + mt * 16 + (lane & 15);
                    int ack = kt * 2 + (lane >> 4);
                    uint32_t ab = ar * 128 + (((uint32_t)(ack ^ (ar & 7))) << 4);
                    ldsm_x4(ah[mt], xb + ab);
                    ldsm_x4(al[mt], xb + 16384 + ab);
                }
                int bn2 = nw * 64 + (lane & 7);
                int bck = kt * 2 + bsel;
                #pragma unroll
                for (int nt = 0; nt < 8; nt++) {
                    if (nt < NT) {
                        int n = bn2 + nt * 8;
                        uint32_t bb = n * 128 + (((uint32_t)(bck ^ (n & 7))) << 4);
                        uint32_t bh2[2], bl2[2];
                        ldsm_x2(bh2, wbh + bb);
                        ldsm_x2(bl2, wbl + bb);
                        #pragma unroll
                        for (int mt = 0; mt < 2; mt++) {
                            mma16816(rs[mt][nt], ah[mt], bh2[0], bh2[1]);
                            mma16816(rs[mt][nt], ah[mt], bl2[0], bl2[1]);
                            mma16816(rs[mt][nt], al[mt], bh2[0], bh2[1]);
                        }
                    }
                }
            }
            __syncthreads();
        }

        // res epilogue
        const uint32_t* rInH = (const uint32_t*)resInH;
        const uint32_t* rInL = (const uint32_t*)resInL;
        uint32_t* rOutH = (uint32_t*)resOutH;
        uint32_t* rOutL = (uint32_t*)resOutL;
        #pragma unroll
        for (int nt = 0; nt < 8; nt++) {
            if (nt < NT) {
                int c = nw * 64 + nt * 8 + 2 * (lane & 3);
                float b0 = biasB[240 + c], b1 = biasB[240 + c + 1];
                #pragma unroll
                for (int mt = 0; mt < 2; mt++) {
                    #pragma unroll
                    for (int rh = 0; rh < 2; rh++) {
                        int t = t0 + mw * 32 + mt * 16 + (lane >> 2) + rh * 8;
                        size_t ri = ((size_t)b * TLEN + t) * 64 + (c >> 1);
                        U1B vh, vl, oh, ol;
                        vh.u = rInH[ri]; vl.u = rInL[ri];
                        float o0 = rs[mt][nt][rh * 2 + 0] + b0
                                 + __bfloat162float(vh.h[0]) + __bfloat162float(vl.h[0]);
                        float o1 = rs[mt][nt][rh * 2 + 1] + b1
                                 + __bfloat162float(vh.h[1]) + __bfloat162float(vl.h[1]);
                        split_bf16(o0, oh.h[0], ol.h[0]);
                        split_bf16(o1, oh.h[1], ol.h[1]);
                        rOutH[ri] = oh.u;
                        rOutL[ri] = ol.u;
                    }
                }
            }
        }
    }
    // zero pad channels 120-127 of resOut
    if (tid < 128) {
        size_t rp = ((size_t)b * TLEN + t0 + tid) * 16 + 15;
        resOutH[rp] = make_uint4(0, 0, 0, 0);
        resOutL[rp] = make_uint4(0, 0, 0, 0);
    }
}

// ---------------- fused mma head kernel (unchanged from R9/R10) -----------
#define HOFF_OB   0
#define HOFF_EB   1024
#define HOFF_A1H  2048
#define HOFF_A1L  18432
#define HOFF_WHH  34816
#define HOFF_WHL  67584
#define HOFF_A2H  100352
#define HOFF_A2L  165888
#define SMEM_HEAD 231424

__global__ void __launch_bounds__(256, 1) head_mma(
    const float* __restrict__ out_b, const float* __restrict__ end_b,
    float* __restrict__ out)
{
    extern __shared__ __align__(16) char sm[];
    const uint32_t smb = smem_u32(sm);
    const int tid  = threadIdx.x;
    const int lane = tid & 31;
    const int wid  = tid >> 5;
    const int mw   = wid >> 1;
    const int nw   = wid & 1;
    const int b    = blockIdx.y;
    const int t0   = blockIdx.x * 128;

    float* obs = (float*)(sm + HOFF_OB);
    float* ebs = (float*)(sm + HOFF_EB);
    for (int e = tid; e < 256; e += 256) { obs[e] = out_b[e]; ebs[e] = end_b[e]; }

    float ac[2][16][4];
    #pragma unroll
    for (int mt = 0; mt < 2; mt++)
        #pragma unroll
        for (int nt = 0; nt < 16; nt++)
            #pragma unroll
            for (int e = 0; e < 4; e++) ac[mt][nt][e] = 0.f;

    for (int q = 0; q < 4; q++) {
        __syncthreads();
        for (int e = tid; e < 1024; e += 256) {
            int r = e >> 3, ii = e & 7;
            int c0 = q * 64 + ii * 8;
            U4B uh, ul;
            if (c0 < 240) {
                size_t gi = ((size_t)b * TLEN + t0 + r) * 240 + c0;
                float4 v0 = *(const float4*)(g_skip + gi);
                float4 v1 = *(const float4*)(g_skip + gi + 4);
                float vv[8] = {v0.x, v0.y, v0.z, v0.w, v1.x, v1.y, v1.z, v1.w};
                #pragma unroll
                for (int k = 0; k < 8; k++)
                    split_bf16(fmaxf(vv[k], 0.f), uh.h[k], ul.h[k]);
            } else {
                uh.u = make_uint4(0,0,0,0); ul.u = make_uint4(0,0,0,0);
            }
            uint32_t byte = sw128((r << 7) + (ii << 4));
            *(uint4*)(sm + HOFF_A1H + byte) = uh.u;
            *(uint4*)(sm + HOFF_A1L + byte) = ul.u;
        }
        for (int e = tid; e < 2048; e += 256) {
            ((uint4*)(sm + HOFF_WHH))[e] = g_Woh[q * 2048 + e];
            ((uint4*)(sm + HOFF_WHL))[e] = g_Wol[q * 2048 + e];
        }
        __syncthreads();
        #pragma unroll
        for (int kt = 0; kt < 4; kt++) {
            uint32_t ah[2][4], al[2][4];
            #pragma unroll
            for (int mt = 0; mt < 2; mt++) {
                int ar = mw * 32 + mt * 16 + (lane & 15);
                int ack = kt * 2 + (lane >> 4);
                uint32_t ab = ar * 128 + (((uint32_t)(ack ^ (ar & 7))) << 4);
                ldsm_x4(ah[mt], smb + HOFF_A1H + ab);
                ldsm_x4(al[mt], smb + HOFF_A1L + ab);
            }
            int bn = nw * 128 + (lane & 7);
            int bsel = (lane >> 3) & 1;
            #pragma unroll
            for (int nt = 0; nt < 16; nt++) {
                int n = bn + nt * 8;
                int bck = kt * 2 + bsel;
                uint32_t bb = n * 128 + (((uint32_t)(bck ^ (n & 7))) << 4);
                uint32_t bh[2], bl[2];
                ldsm_x2(bh, smb + HOFF_WHH + bb);
                ldsm_x2(bl, smb + HOFF_WHL + bb);
                #pragma unroll
                for (int mt = 0; mt < 2; mt++) {
                    mma16816(ac[mt][nt], ah[mt], bh[0], bh[1]);
                    mma16816(ac[mt][nt], ah[mt], bl[0], bl[1]);
                    mma16816(ac[mt][nt], al[mt], bh[0], bh[1]);
                }
            }
        }
    }

    __syncthreads();
    #pragma unroll
    for (int nt = 0; nt < 16; nt++) {
        int p = nw * 128 + nt * 8 + 2 * (lane & 3);
        int chunk = p >> 6;
        int p2 = p & 63;
        float b0 = obs[p], b1 = obs[p + 1];
        #pragma unroll
        for (int mt = 0; mt < 2; mt++) {
            #pragma unroll
            for (int rh = 0; rh < 2; rh++) {
                int r = mw * 32 + mt * 16 + (lane >> 2) + rh * 8;
                float v0 = fmaxf(ac[mt][nt][rh * 2 + 0] + b0, 0.f);
                float v1 = fmaxf(ac[mt][nt][rh * 2 + 1] + b1, 0.f);
                U1B ph, pl;
                split_bf16(v0, ph.h[0], pl.h[0]);
                split_bf16(v1, ph.h[1], pl.h[1]);
                uint32_t byte = r * 128 + (((uint32_t)((p2 >> 3) ^ (r & 7))) << 4)
                              + (p2 & 7) * 2;
                *(uint32_t*)(sm + HOFF_A2H + chunk * 16384 + byte) = ph.u;
                *(uint32_t*)(sm + HOFF_A2L + chunk * 16384 + byte) = pl.u;
            }
        }
    }

    #pragma unroll
    for (int mt = 0; mt < 2; mt++)
        #pragma unroll
        for (int nt = 0; nt < 16; nt++)
            #pragma unroll
            for (int e = 0; e < 4; e++) ac[mt][nt][e] = 0.f;

    for (int q = 0; q < 4; q++) {
        __syncthreads();
        for (int e = tid; e < 2048; e += 256) {
            ((uint4*)(sm + HOFF_WHH))[e] = g_Weh[q * 2048 + e];
            ((uint4*)(sm + HOFF_WHL))[e] = g_Wel[q * 2048 + e];
        }
        __syncthreads();
        #pragma unroll
        for (int kt = 0; kt < 4; kt++) {
            uint32_t ah[2][4], al[2][4];
            #pragma unroll
            for (int mt = 0; mt < 2; mt++) {
                int ar = mw * 32 + mt * 16 + (lane & 15);
                int ack = kt * 2 + (lane >> 4);
                uint32_t ab = ar * 128 + (((uint32_t)(ack ^ (ar & 7))) << 4);
                ldsm_x4(ah[mt], smb + HOFF_A2H + q * 16384 + ab);
                ldsm_x4(al[mt], smb + HOFF_A2L + q * 16384 + ab);
            }
            int bn = nw * 128 + (lane & 7);
            int bsel = (lane >> 3) & 1;
            #pragma unroll
            for (int nt = 0; nt < 16; nt++) {
                int n = bn + nt * 8;
                int bck = kt * 2 + bsel;
                uint32_t bb = n * 128 + (((uint32_t)(bck ^ (n & 7))) << 4);
                uint32_t bh[2], bl[2];
                ldsm_x2(bh, smb + HOFF_WHH + bb);
                ldsm_x2(bl, smb + HOFF_WHL + bb);
                #pragma unroll
                for (int mt = 0; mt < 2; mt++) {
                    mma16816(ac[mt][nt], ah[mt], bh[0], bh[1]);
                    mma16816(ac[mt][nt], ah[mt], bl[0], bl[1]);
                    mma16816(ac[mt][nt], al[mt], bh[0], bh[1]);
                }
            }
        }
    }

    #pragma unroll
    for (int nt = 0; nt < 16; nt++) {
        int o0 = nw * 128 + nt * 8 + 2 * (lane & 3);
        float b0 = ebs[o0], b1 = ebs[o0 + 1];
        #pragma unroll
        for (int mt = 0; mt < 2; mt++) {
            #pragma unroll
            for (int rh = 0; rh < 2; rh++) {
                int t = t0 + mw * 32 + mt * 16 + (lane >> 2) + rh * 8;
                out[((size_t)b * NC + o0) * TLEN + t]     = ac[mt][nt][rh * 2 + 0] + b0;
                out[((size_t)b * NC + o0 + 1) * TLEN + t] = ac[mt][nt][rh * 2 + 1] + b1;
            }
        }
    }
}

// ---------------- host launcher -------------------------------------------
extern "C" void kernel_launch(void* const* d_in, const int* in_sizes, int n_in,
                              void* d_out, int out_size) {
    const float* wav    = (const float*)d_in[0];
    const float* cond   = (const float*)d_in[1];
    const float* wav_w  = (const float*)d_in[2];
    const float* wav_b  = (const float*)d_in[3];
    const float* cond_w = (const float*)d_in[4];
    const float* cond_b = (const float*)d_in[5];
    const float* dil_w  = (const float*)d_in[6];
    const float* dil_b  = (const float*)d_in[7];
    const float* skip_w = (const float*)d_in[8];
    const float* skip_b = (const float*)d_in[9];
    const float* res_w  = (const float*)d_in[10];
    const float* res_b  = (const float*)d_in[11];
    const float* out_w  = (const float*)d_in[12];
    const float* out_b  = (const float*)d_in[13];
    const float* end_w  = (const float*)d_in[14];
    const float* end_b  = (const float*)d_in[15];

    cudaFuncSetAttribute(block_mma, cudaFuncAttributeMaxDynamicSharedMemorySize,
                         SMEM_MMA);
    cudaFuncSetAttribute(head_mma, cudaFuncAttributeMaxDynamicSharedMemorySize,
                         SMEM_HEAD);

    repack_w1<<<(NBLK * 5 * 240 * 64 + 255) / 256, 256>>>(dil_w, cond_w);
    repack_w2<<<(NBLK * 2 * (240 + 120) * 64 + 255) / 256, 256>>>(skip_w, res_w);
    repack_whead<<<(2 * 4 * 256 * 64 + 255) / 256, 256>>>(out_w, end_w);
    prologue_res<<<(BB * TLEN * 16 + 255) / 256, 256>>>(wav, wav_w, wav_b);
    prologue_cond<<<(BB * TLEN * 16 + 255) / 256, 256>>>(cond);

    dim3 gridB(TLEN / 128, BB);
    for (int i = 0; i < NBLK; i++) {
        int d = 1 << (i % 8);
        block_mma<<<gridB, 256, SMEM_MMA>>>(dil_b, cond_b, skip_b, res_b,
                                            i, d, (i == 0) ? 1 : 0, i & 1);
    }
    head_mma<<<gridB, 256, SMEM_HEAD>>>(out_b, end_b, (float*)d_out);
}

// round 12
// speedup vs baseline: 2.1178x; 1.3769x over previous
#include <cuda_runtime.h>
#include <cuda_fp16.h>
#include <math.h>
#include <stdint.h>

#define BB   4
#define TLEN 32768
#define NM   80
#define RC   120
#define SC   240
#define NBLK 16
#define NC   256

// ---------------- device scratch (no allocations allowed) ----------------
// res as fp16 hi/lo pair (carry precision ~2^-22); MMA consumes hi only.
__device__ uint4 g_resAH[BB * TLEN * 16];
__device__ uint4 g_resAL[BB * TLEN * 16];
__device__ uint4 g_resBH[BB * TLEN * 16];
__device__ uint4 g_resBL[BB * TLEN * 16];
__device__ uint4 g_condH[BB * TLEN * 16];   // cond: single fp16
__device__ float g_skip [BB * TLEN * SC];   // [b][t][c]
__device__ uint4 g_W1h[NBLK * 5 * 1920];    // phase1 fp16, K packed 320
__device__ uint4 g_W2sh[NBLK * 2 * 1920];   // skip [240][64] fp16
__device__ uint4 g_W2rh[NBLK * 2 * 960];    // res  [120][64] fp16
__device__ uint4 g_Woh[4 * 2048];           // out_w [256][64] chunks fp16
__device__ uint4 g_Weh[4 * 2048];           // end_w [256][64] chunks fp16

// ---------------- helpers -------------------------------------------------
__device__ __forceinline__ uint32_t smem_u32(const void* p) {
    uint32_t a;
    asm("{ .reg .u64 t; cvta.to.shared.u64 t, %1; cvt.u32.u64 %0, t; }"
        : "=r"(a) : "l"(p));
    return a;
}
__device__ __forceinline__ uint32_t sw128(uint32_t b) { return b ^ ((b >> 3) & 0x70); }

union U4H { uint4 u; __half h[8]; };
union U1H { uint32_t u; __half h[2]; };

__device__ __forceinline__ void split_fp16(float x, __half& hi, __half& lo) {
    hi = __float2half(x);
    lo = __float2half(x - __half2float(hi));
}
__device__ __forceinline__ float fast_tanh(float x) {
    return 1.f - 2.f / (1.f + __expf(2.f * x));
}
__device__ __forceinline__ float fast_sigmoid(float x) {
    return 1.f / (1.f + __expf(-x));
}

__device__ __forceinline__ void ldsm_x4(uint32_t* r, uint32_t addr) {
    asm volatile("ldmatrix.sync.aligned.m8n8.x4.shared.b16 {%0,%1,%2,%3}, [%4];"
                 : "=r"(r[0]), "=r"(r[1]), "=r"(r[2]), "=r"(r[3]) : "r"(addr));
}
__device__ __forceinline__ void ldsm_x2(uint32_t* r, uint32_t addr) {
    asm volatile("ldmatrix.sync.aligned.m8n8.x2.shared.b16 {%0,%1}, [%2];"
                 : "=r"(r[0]), "=r"(r[1]) : "r"(addr));
}
__device__ __forceinline__ void mma16816(float* c, const uint32_t* a,
                                         uint32_t b0, uint32_t b1) {
    asm("mma.sync.aligned.m16n8k16.row.col.f32.f16.f16.f32 "
        "{%0,%1,%2,%3}, {%4,%5,%6,%7}, {%8,%9}, {%0,%1,%2,%3};"
        : "+f"(c[0]), "+f"(c[1]), "+f"(c[2]), "+f"(c[3])
        : "r"(a[0]), "r"(a[1]), "r"(a[2]), "r"(a[3]), "r"(b0), "r"(b1));
}
__device__ __forceinline__ void cpa16(uint32_t smem, const void* gmem, uint32_t ssz) {
    asm volatile("cp.async.cg.shared.global [%0], [%1], 16, %2;"
                 :: "r"(smem), "l"(gmem), "r"(ssz) : "memory");
}
#define CPA_COMMIT() asm volatile("cp.async.commit_group;" ::: "memory")
template <int N> __device__ __forceinline__ void cpa_wait() {
    asm volatile("cp.async.wait_group %0;" :: "n"(N) : "memory");
}

// ---------------- weight repack kernels -----------------------------------
// phase1 K packed: k 0..119 = dil tap0, 120..239 = dil tap1, 240..319 = cond
__global__ void repack_w1(const float* __restrict__ dil_w,
                          const float* __restrict__ cond_w) {
    int idx = blockIdx.x * blockDim.x + threadIdx.x;
    const int total = NBLK * 5 * 240 * 64;
    if (idx >= total) return;
    int kk = idx & 63;
    int n  = (idx >> 6) % 240;
    int q  = (idx / (64 * 240)) % 5;
    int i  = idx / (64 * 240 * 5);
    int c  = (n >> 1) + (n & 1) * 120;          // original output channel
    int kpos = q * 64 + kk;
    float w;
    if (kpos < 120)      w = dil_w[((i*240 + c)*120 + kpos)*2 + 0];
    else if (kpos < 240) w = dil_w[((i*240 + c)*120 + (kpos - 120))*2 + 1];
    else                 w = cond_w[(i*240 + c)*80 + (kpos - 240)];
    int elem = sw128(n * 128 + kk * 2) >> 1;
    size_t base = (size_t)(i * 5 + q) * 15360;
    ((__half*)g_W1h)[base + elem] = __float2half(w);
}

__global__ void repack_w2(const float* __restrict__ skip_w,
                          const float* __restrict__ res_w) {
    int idx = blockIdx.x * blockDim.x + threadIdx.x;
    const int totS = NBLK * 2 * 240 * 64;
    const int totR = NBLK * 2 * 120 * 64;
    if (idx < totS) {
        int kk = idx & 63;
        int c  = (idx >> 6) % 240;
        int q  = (idx / (64 * 240)) % 2;
        int i  = idx / (64 * 240 * 2);
        int k  = q * 64 + kk;
        float w = (k < 120) ? skip_w[(i*240 + c)*120 + k] : 0.f;
        int elem = sw128(c * 128 + kk * 2) >> 1;
        size_t base = (size_t)(i * 2 + q) * 15360;
        ((__half*)g_W2sh)[base + elem] = __float2half(w);
    } else if (idx < totS + totR) {
        int j = idx - totS;
        int kk = j & 63;
        int c  = (j >> 6) % 120;
        int q  = (j / (64 * 120)) % 2;
        int i  = j / (64 * 120 * 2);
        int k  = q * 64 + kk;
        float w = (k < 120) ? res_w[(i*120 + c)*120 + k] : 0.f;
        int elem = sw128(c * 128 + kk * 2) >> 1;
        size_t base = (size_t)(i * 2 + q) * 7680;
        ((__half*)g_W2rh)[base + elem] = __float2half(w);
    }
}

__global__ void repack_whead(const float* __restrict__ out_w,
                             const float* __restrict__ end_w) {
    int idx = blockIdx.x * blockDim.x + threadIdx.x;
    const int half = 4 * 256 * 64;
    if (idx >= 2 * half) return;
    int sel = idx / half;
    int j = idx % half;
    int kk = j & 63;
    int n  = (j >> 6) % 256;
    int q  = j / (64 * 256);
    int k  = q * 64 + kk;
    float w;
    if (sel == 0) w = (k < 240) ? out_w[n * 240 + k] : 0.f;
    else          w = end_w[n * 256 + k];
    int elem = sw128(n * 128 + kk * 2) >> 1;
    size_t base = (size_t)q * 16384;
    if (sel == 0) ((__half*)g_Woh)[base + elem] = __float2half(w);
    else          ((__half*)g_Weh)[base + elem] = __float2half(w);
}

// ---------------- prologues -----------------------------------------------
__global__ void prologue_res(const float* __restrict__ wav,
                             const float* __restrict__ wav_w,
                             const float* __restrict__ wav_b) {
    int idx = blockIdx.x * blockDim.x + threadIdx.x;
    const int total = BB * TLEN * 16;
    if (idx >= total) return;
    int chunk = idx & 15;
    int t = (idx >> 4) % TLEN;
    int b = idx / (TLEN * 16);
    float wv = wav[(size_t)b * TLEN + t];
    U4H uh, ul;
    #pragma unroll
    for (int e = 0; e < 8; e++) {
        int c = chunk * 8 + e;
        float v = (c < RC) ? (wav_w[c] * wv + wav_b[c]) : 0.f;
        split_fp16(v, uh.h[e], ul.h[e]);
    }
    g_resAH[idx] = uh.u;
    g_resAL[idx] = ul.u;
}

__global__ void prologue_cond(const float* __restrict__ cond) {
    int idx = blockIdx.x * blockDim.x + threadIdx.x;
    const int total = BB * TLEN * 16;
    if (idx >= total) return;
    int chunk = idx & 15;
    int t = (idx >> 4) % TLEN;
    int b = idx / (TLEN * 16);
    U4H uh;
    #pragma unroll
    for (int e = 0; e < 8; e++) {
        int c = chunk * 8 + e;
        float v = (c < NM) ? cond[((size_t)b * NM + c) * TLEN + t] : 0.f;
        uh.h[e] = __float2half(v);
    }
    g_condH[idx] = uh.u;
}

// ---------------- mma per-layer kernel (fp16 single, cp.async) ------------
#define OFF_BA   0
#define OFF_BB   1024
#define OFF_X    4096
#define XBUF(i)  (OFF_X + (i) * 16384)          // [128][64] fp16 = 16KB
#define OFF_W    36864
#define WBUF(i)  (OFF_W + (i) * 30720)          // [240][64] fp16
#define SMEM_MMA 98304

__global__ void __launch_bounds__(256, 1) block_mma(
    const float* __restrict__ dil_b, const float* __restrict__ cond_b,
    const float* __restrict__ skip_b, const float* __restrict__ res_b,
    int layer, int d, int first, int swap)
{
    extern __shared__ __align__(16) char sm[];
    const uint32_t smb = smem_u32(sm);
    const int tid  = threadIdx.x;
    const int lane = tid & 31;
    const int wid  = tid >> 5;
    const int mw   = wid >> 1;            // 0..3 (m)
    const int nw   = wid & 1;             // 0..1 (n)
    const int b    = blockIdx.y;
    const int t0   = blockIdx.x * 128;

    const uint4* resInH = swap ? g_resBH : g_resAH;
    const uint4* resInL = swap ? g_resBL : g_resAL;
    uint4* resOutH = swap ? g_resAH : g_resBH;
    uint4* resOutL = swap ? g_resAL : g_resBL;

    // ---- staging helpers ----
    auto stage1 = [&](int q) {    // K-packed: kg<15 shift-res | <30 res | cond
        uint32_t xb = smb + XBUF(q & 1);
        for (int e = tid; e < 1024; e += 256) {
            int r = e >> 3, ii = e & 7;
            int kg = q * 8 + ii;
            const uint4* sH; int t; int grp;
            if (kg < 15)      { sH = resInH;  t = t0 - d + r; grp = kg; }
            else if (kg < 30) { sH = resInH;  t = t0 + r;     grp = kg - 15; }
            else              { sH = g_condH; t = t0 + r;     grp = kg - 30; }
            uint32_t ok = (t >= 0) ? 16u : 0u;
            int tc = (t >= 0) ? t : 0;
            size_t si = ((size_t)b * TLEN + tc) * 16 + grp;
            uint32_t byte = sw128((r << 7) + (ii << 4));
            cpa16(xb + byte, sH + si, ok);
        }
        uint32_t wb = smb + WBUF(q & 1);
        size_t wgb = (size_t)(layer * 5 + q) * 1920;
        for (int e = tid; e < 1920; e += 256)
            cpa16(wb + e * 16, g_W1h + wgb + e, 16);
        CPA_COMMIT();
    };
    auto stage2s = [&](int chunk, int buf) {
        uint32_t wb = smb + WBUF(buf);
        size_t bs = (size_t)(layer * 2 + chunk) * 1920;
        for (int e = tid; e < 1920; e += 256)
            cpa16(wb + e * 16, g_W2sh + bs + e, 16);
        CPA_COMMIT();
    };
    auto stage2r = [&](int chunk, int buf) {
        uint32_t wb = smb + WBUF(buf);
        size_t br = (size_t)(layer * 2 + chunk) * 960;
        for (int e = tid; e < 960; e += 256)
            cpa16(wb + e * 16, g_W2rh + br + e, 16);
        CPA_COMMIT();
    };

    stage1(0);

    float* biasA = (float*)(sm + OFF_BA);
    float* biasB = (float*)(sm + OFF_BB);
    for (int e = tid; e < 240; e += 256)
        biasA[e] = dil_b[layer * 240 + e] + cond_b[layer * 240 + e];
    for (int e = tid; e < 360; e += 256)
        biasB[e] = (e < 240) ? skip_b[layer * 240 + e] : res_b[layer * 120 + e - 240];

    // ========== phase 1: g[128t x 240n(permuted)], K=320 ==========
    float ac[2][15][4];
    #pragma unroll
    for (int mt = 0; mt < 2; mt++)
        #pragma unroll
        for (int nt = 0; nt < 15; nt++)
            #pragma unroll
            for (int e = 0; e < 4; e++) ac[mt][nt][e] = 0.f;

    const int bn   = nw * 120 + (lane & 7);
    const int bhi  = (lane >> 4) << 3;
    const int bsel = (lane >> 3) & 1;

    for (int q = 0; q < 5; q++) {
        if (q < 4) stage1(q + 1);
        else       stage2s(0, 1);
        cpa_wait<1>();
        __syncthreads();
        uint32_t xb  = smb + XBUF(q & 1);
        uint32_t wbh = smb + WBUF(q & 1);
        #pragma unroll
        for (int kt = 0; kt < 4; kt++) {
            uint32_t ah[2][4];
            #pragma unroll
            for (int mt = 0; mt < 2; mt++) {
                int ar = mw * 32 + mt * 16 + (lane & 15);
                int ack = kt * 2 + (lane >> 4);
                uint32_t ab = ar * 128 + (((uint32_t)(ack ^ (ar & 7))) << 4);
                ldsm_x4(ah[mt], xb + ab);
            }
            int bck = kt * 2 + bsel;
            #pragma unroll
            for (int j = 0; j < 7; j++) {
                int n0 = bn + j * 16 + bhi;
                uint32_t bb = n0 * 128 + (((uint32_t)(bck ^ (n0 & 7))) << 4);
                uint32_t bq[4];
                ldsm_x4(bq, wbh + bb);
                #pragma unroll
                for (int mt = 0; mt < 2; mt++) {
                    mma16816(ac[mt][2*j],   ah[mt], bq[0], bq[1]);
                    mma16816(ac[mt][2*j+1], ah[mt], bq[2], bq[3]);
                }
            }
            {   // nt = 14
                int n = nw * 120 + 112 + (lane & 7);
                uint32_t bb = n * 128 + (((uint32_t)(bck ^ (n & 7))) << 4);
                uint32_t bh2[2];
                ldsm_x2(bh2, wbh + bb);
                #pragma unroll
                for (int mt = 0; mt < 2; mt++)
                    mma16816(ac[mt][14], ah[mt], bh2[0], bh2[1]);
            }
        }
        __syncthreads();
    }

    // ========== gating (registers) -> A2 tile (fp16) in X buffers ==========
    #pragma unroll
    for (int nt = 0; nt < 15; nt++) {
        int p = nw * 60 + nt * 4 + (lane & 3);
        int reg = (p < 64) ? 0 : 1;
        int p2 = p & 63;
        float ba_t = biasA[p];
        float ba_s = biasA[p + 120];
        #pragma unroll
        for (int mt = 0; mt < 2; mt++) {
            #pragma unroll
            for (int rh = 0; rh < 2; rh++) {
                int r = mw * 32 + mt * 16 + (lane >> 2) + rh * 8;
                float gt = ac[mt][nt][rh * 2 + 0] + ba_t;
                float gs = ac[mt][nt][rh * 2 + 1] + ba_s;
                float v = fast_tanh(gt) * fast_sigmoid(gs);
                uint32_t byte = r * 128 + (((uint32_t)((p2 >> 3) ^ (r & 7))) << 4)
                              + (p2 & 7) * 2;
                *(__half*)(sm + XBUF(reg) + byte) = __float2half(v);
            }
        }
    }
    // zero-pad A2 chunk1 (p 120..127)
    if (tid < 128) {
        uint32_t byte = tid * 128 + ((7u ^ (tid & 7)) << 4);
        *(uint4*)(sm + XBUF(1) + byte) = make_uint4(0, 0, 0, 0);
    }

    // ========== phase 2a: skip[128t x 240c], K=120 ==========
    float sk[2][15][4];
    #pragma unroll
    for (int mt = 0; mt < 2; mt++)
        #pragma unroll
        for (int nt = 0; nt < 15; nt++)
            #pragma unroll
            for (int e = 0; e < 4; e++) sk[mt][nt][e] = 0.f;

    for (int q2 = 0; q2 < 2; q2++) {
        if (q2 == 0) stage2s(1, 0);
        else         stage2r(0, 1);
        cpa_wait<1>();
        __syncthreads();
        uint32_t xb  = smb + XBUF(q2);
        uint32_t wbh = smb + WBUF(1 - q2);
        #pragma unroll
        for (int kt = 0; kt < 4; kt++) {
            uint32_t ah[2][4];
            #pragma unroll
            for (int mt = 0; mt < 2; mt++) {
                int ar = mw * 32 + mt * 16 + (lane & 15);
                int ack = kt * 2 + (lane >> 4);
                uint32_t ab = ar * 128 + (((uint32_t)(ack ^ (ar & 7))) << 4);
                ldsm_x4(ah[mt], xb + ab);
            }
            int bck = kt * 2 + bsel;
            #pragma unroll
            for (int j = 0; j < 7; j++) {
                int n0 = bn + j * 16 + bhi;
                uint32_t bb = n0 * 128 + (((uint32_t)(bck ^ (n0 & 7))) << 4);
                uint32_t bq[4];
                ldsm_x4(bq, wbh + bb);
                #pragma unroll
                for (int mt = 0; mt < 2; mt++) {
                    mma16816(sk[mt][2*j],   ah[mt], bq[0], bq[1]);
                    mma16816(sk[mt][2*j+1], ah[mt], bq[2], bq[3]);
                }
            }
            {
                int n = nw * 120 + 112 + (lane & 7);
                uint32_t bb = n * 128 + (((uint32_t)(bck ^ (n & 7))) << 4);
                uint32_t bh2[2];
                ldsm_x2(bh2, wbh + bb);
                #pragma unroll
                for (int mt = 0; mt < 2; mt++)
                    mma16816(sk[mt][14], ah[mt], bh2[0], bh2[1]);
            }
        }
        __syncthreads();
    }

    // skip epilogue: [b][t][240] fp32 accumulate
    #pragma unroll
    for (int nt = 0; nt < 15; nt++) {
        int c = nw * 120 + nt * 8 + 2 * (lane & 3);
        float b0 = biasB[c], b1 = biasB[c + 1];
        #pragma unroll
        for (int mt = 0; mt < 2; mt++) {
            #pragma unroll
            for (int rh = 0; rh < 2; rh++) {
                int t = t0 + mw * 32 + mt * 16 + (lane >> 2) + rh * 8;
                size_t gi = ((size_t)b * TLEN + t) * 240 + c;
                float2 v;
                v.x = sk[mt][nt][rh * 2 + 0] + b0;
                v.y = sk[mt][nt][rh * 2 + 1] + b1;
                if (!first) {
                    float2 o = *(float2*)(g_skip + gi);
                    v.x += o.x; v.y += o.y;
                }
                *(float2*)(g_skip + gi) = v;
            }
        }
    }

    // ========== phase 2b: res[128t x 120c], K=120 ==========
    {
        float rs[2][8][4];
        #pragma unroll
        for (int mt = 0; mt < 2; mt++)
            #pragma unroll
            for (int nt = 0; nt < 8; nt++)
                #pragma unroll
                for (int e = 0; e < 4; e++) rs[mt][nt][e] = 0.f;
        const int NT = 8 - nw;

        for (int q2 = 0; q2 < 2; q2++) {
            if (q2 == 0) { stage2r(1, 0); cpa_wait<1>(); }
            else         { cpa_wait<0>(); }
            __syncthreads();
            uint32_t xb  = smb + XBUF(q2);
            uint32_t wbh = smb + WBUF(1 - q2);
            #pragma unroll
            for (int kt = 0; kt < 4; kt++) {
                uint32_t ah[2][4];
                #pragma unroll
                for (int mt = 0; mt < 2; mt++) {
                    int ar = mw * 32 + mt * 16 + (lane & 15);
                    int ack = kt * 2 + (lane >> 4);
                    uint32_t ab = ar * 128 + (((uint32_t)(ack ^ (ar & 7))) << 4);
                    ldsm_x4(ah[mt], xb + ab);
                }
                int bn2 = nw * 64 + (lane & 7);
                int bck = kt * 2 + bsel;
                #pragma unroll
                for (int nt = 0; nt < 8; nt++) {
                    if (nt < NT) {
                        int n = bn2 + nt * 8;
                        uint32_t bb = n * 128 + (((uint32_t)(bck ^ (n & 7))) << 4);
                        uint32_t bh2[2];
                        ldsm_x2(bh2, wbh + bb);
                        #pragma unroll
                        for (int mt = 0; mt < 2; mt++)
                            mma16816(rs[mt][nt], ah[mt], bh2[0], bh2[1]);
                    }
                }
            }
            __syncthreads();
        }

        // res epilogue: resOut = rs + bias + resIn(hi+lo); store fp16 hi/lo
        const uint32_t* rInH = (const uint32_t*)resInH;
        const uint32_t* rInL = (const uint32_t*)resInL;
        uint32_t* rOutH = (uint32_t*)resOutH;
        uint32_t* rOutL = (uint32_t*)resOutL;
        #pragma unroll
        for (int nt = 0; nt < 8; nt++) {
            if (nt < NT) {
                int c = nw * 64 + nt * 8 + 2 * (lane & 3);
                float b0 = biasB[240 + c], b1 = biasB[240 + c + 1];
                #pragma unroll
                for (int mt = 0; mt < 2; mt++) {
                    #pragma unroll
                    for (int rh = 0; rh < 2; rh++) {
                        int t = t0 + mw * 32 + mt * 16 + (lane >> 2) + rh * 8;
                        size_t ri = ((size_t)b * TLEN + t) * 64 + (c >> 1);
                        U1H vh, vl, oh, ol;
                        vh.u = rInH[ri]; vl.u = rInL[ri];
                        float o0 = rs[mt][nt][rh * 2 + 0] + b0
                                 + __half2float(vh.h[0]) + __half2float(vl.h[0]);
                        float o1 = rs[mt][nt][rh * 2 + 1] + b1
                                 + __half2float(vh.h[1]) + __half2float(vl.h[1]);
                        split_fp16(o0, oh.h[0], ol.h[0]);
                        split_fp16(o1, oh.h[1], ol.h[1]);
                        rOutH[ri] = oh.u;
                        rOutL[ri] = ol.u;
                    }
                }
            }
        }
    }
    // zero pad channels 120-127 of resOut
    if (tid < 128) {
        size_t rp = ((size_t)b * TLEN + t0 + tid) * 16 + 15;
        resOutH[rp] = make_uint4(0, 0, 0, 0);
        resOutL[rp] = make_uint4(0, 0, 0, 0);
    }
}

// ---------------- fused mma head kernel (fp16 single) ---------------------
#define HOFF_OB   0
#define HOFF_EB   1024
#define HOFF_A1   2048      // [128][64] fp16 = 16384
#define HOFF_WH   18432     // [256][64] fp16 = 32768
#define HOFF_A2   51200     // [4][128][64] fp16 = 65536
#define SMEM_HEAD 116736

__global__ void __launch_bounds__(256, 1) head_mma(
    const float* __restrict__ out_b, const float* __restrict__ end_b,
    float* __restrict__ out)
{
    extern __shared__ __align__(16) char sm[];
    const uint32_t smb = smem_u32(sm);
    const int tid  = threadIdx.x;
    const int lane = tid & 31;
    const int wid  = tid >> 5;
    const int mw   = wid >> 1;
    const int nw   = wid & 1;
    const int b    = blockIdx.y;
    const int t0   = blockIdx.x * 128;

    float* obs = (float*)(sm + HOFF_OB);
    float* ebs = (float*)(sm + HOFF_EB);
    for (int e = tid; e < 256; e += 256) { obs[e] = out_b[e]; ebs[e] = end_b[e]; }

    float ac[2][16][4];
    #pragma unroll
    for (int mt = 0; mt < 2; mt++)
        #pragma unroll
        for (int nt = 0; nt < 16; nt++)
            #pragma unroll
            for (int e = 0; e < 4; e++) ac[mt][nt][e] = 0.f;

    for (int q = 0; q < 4; q++) {
        __syncthreads();
        for (int e = tid; e < 1024; e += 256) {
            int r = e >> 3, ii = e & 7;
            int c0 = q * 64 + ii * 8;
            U4H uh;
            if (c0 < 240) {
                size_t gi = ((size_t)b * TLEN + t0 + r) * 240 + c0;
                float4 v0 = *(const float4*)(g_skip + gi);
                float4 v1 = *(const float4*)(g_skip + gi + 4);
                float vv[8] = {v0.x, v0.y, v0.z, v0.w, v1.x, v1.y, v1.z, v1.w};
                #pragma unroll
                for (int k = 0; k < 8; k++)
                    uh.h[k] = __float2half(fmaxf(vv[k], 0.f));
            } else {
                uh.u = make_uint4(0,0,0,0);
            }
            uint32_t byte = sw128((r << 7) + (ii << 4));
            *(uint4*)(sm + HOFF_A1 + byte) = uh.u;
        }
        for (int e = tid; e < 2048; e += 256)
            ((uint4*)(sm + HOFF_WH))[e] = g_Woh[q * 2048 + e];
        __syncthreads();
        #pragma unroll
        for (int kt = 0; kt < 4; kt++) {
            uint32_t ah[2][4];
            #pragma unroll
            for (int mt = 0; mt < 2; mt++) {
                int ar = mw * 32 + mt * 16 + (lane & 15);
                int ack = kt * 2 + (lane >> 4);
                uint32_t ab = ar * 128 + (((uint32_t)(ack ^ (ar & 7))) << 4);
                ldsm_x4(ah[mt], smb + HOFF_A1 + ab);
            }
            int bn = nw * 128 + (lane & 7);
            int bhi2 = (lane >> 4) << 3;
            int bsel = (lane >> 3) & 1;
            int bck = kt * 2 + bsel;
            #pragma unroll
            for (int j = 0; j < 8; j++) {
                int n0 = bn + j * 16 + bhi2;
                uint32_t bb = n0 * 128 + (((uint32_t)(bck ^ (n0 & 7))) << 4);
                uint32_t bq[4];
                ldsm_x4(bq, smb + HOFF_WH + bb);
                #pragma unroll
                for (int mt = 0; mt < 2; mt++) {
                    mma16816(ac[mt][2*j],   ah[mt], bq[0], bq[1]);
                    mma16816(ac[mt][2*j+1], ah[mt], bq[2], bq[3]);
                }
            }
        }
    }

    __syncthreads();
    #pragma unroll
    for (int nt = 0; nt < 16; nt++) {
        int p = nw * 128 + nt * 8 + 2 * (lane & 3);
        int chunk = p >> 6;
        int p2 = p & 63;
        float b0 = obs[p], b1 = obs[p + 1];
        #pragma unroll
        for (int mt = 0; mt < 2; mt++) {
            #pragma unroll
            for (int rh = 0; rh < 2; rh++) {
                int r = mw * 32 + mt * 16 + (lane >> 2) + rh * 8;
                float v0 = fmaxf(ac[mt][nt][rh * 2 + 0] + b0, 0.f);
                float v1 = fmaxf(ac[mt][nt][rh * 2 + 1] + b1, 0.f);
                U1H ph;
                ph.h[0] = __float2half(v0);
                ph.h[1] = __float2half(v1);
                uint32_t byte = r * 128 + (((uint32_t)((p2 >> 3) ^ (r & 7))) << 4)
                              + (p2 & 7) * 2;
                *(uint32_t*)(sm + HOFF_A2 + chunk * 16384 + byte) = ph.u;
            }
        }
    }

    #pragma unroll
    for (int mt = 0; mt < 2; mt++)
        #pragma unroll
        for (int nt = 0; nt < 16; nt++)
            #pragma unroll
            for (int e = 0; e < 4; e++) ac[mt][nt][e] = 0.f;

    for (int q = 0; q < 4; q++) {
        __syncthreads();
        for (int e = tid; e < 2048; e += 256)
            ((uint4*)(sm + HOFF_WH))[e] = g_Weh[q * 2048 + e];
        __syncthreads();
        #pragma unroll
        for (int kt = 0; kt < 4; kt++) {
            uint32_t ah[2][4];
            #pragma unroll
            for (int mt = 0; mt < 2; mt++) {
                int ar = mw * 32 + mt * 16 + (lane & 15);
                int ack = kt * 2 + (lane >> 4);
                uint32_t ab = ar * 128 + (((uint32_t)(ack ^ (ar & 7))) << 4);
                ldsm_x4(ah[mt], smb + HOFF_A2 + q * 16384 + ab);
            }
            int bn = nw * 128 + (lane & 7);
            int bhi2 = (lane >> 4) << 3;
            int bsel = (lane >> 3) & 1;
            int bck = kt * 2 + bsel;
            #pragma unroll
            for (int j = 0; j < 8; j++) {
                int n0 = bn + j * 16 + bhi2;
                uint32_t bb = n0 * 128 + (((uint32_t)(bck ^ (n0 & 7))) << 4);
                uint32_t bq[4];
                ldsm_x4(bq, smb + HOFF_WH + bb);
                #pragma unroll
                for (int mt = 0; mt < 2; mt++) {
                    mma16816(ac[mt][2*j],   ah[mt], bq[0], bq[1]);
                    mma16816(ac[mt][2*j+1], ah[mt], bq[2], bq[3]);
                }
            }
        }
    }

    #pragma unroll
    for (int nt = 0; nt < 16; nt++) {
        int o0 = nw * 128 + nt * 8 + 2 * (lane & 3);
        float b0 = ebs[o0], b1 = ebs[o0 + 1];
        #pragma unroll
        for (int mt = 0; mt < 2; mt++) {
            #pragma unroll
            for (int rh = 0; rh < 2; rh++) {
                int t = t0 + mw * 32 + mt * 16 + (lane >> 2) + rh * 8;
                out[((size_t)b * NC + o0) * TLEN + t]     = ac[mt][nt][rh * 2 + 0] + b0;
                out[((size_t)b * NC + o0 + 1) * TLEN + t] = ac[mt][nt][rh * 2 + 1] + b1;
            }
        }
    }
}

// ---------------- host launcher -------------------------------------------
extern "C" void kernel_launch(void* const* d_in, const int* in_sizes, int n_in,
                              void* d_out, int out_size) {
    const float* wav    = (const float*)d_in[0];
    const float* cond   = (const float*)d_in[1];
    const float* wav_w  = (const float*)d_in[2];
    const float* wav_b  = (const float*)d_in[3];
    const float* cond_w = (const float*)d_in[4];
    const float* cond_b = (const float*)d_in[5];
    const float* dil_w  = (const float*)d_in[6];
    const float* dil_b  = (const float*)d_in[7];
    const float* skip_w = (const float*)d_in[8];
    const float* skip_b = (const float*)d_in[9];
    const float* res_w  = (const float*)d_in[10];
    const float* res_b  = (const float*)d_in[11];
    const float* out_w  = (const float*)d_in[12];
    const float* out_b  = (const float*)d_in[13];
    const float* end_w  = (const float*)d_in[14];
    const float* end_b  = (const float*)d_in[15];

    cudaFuncSetAttribute(block_mma, cudaFuncAttributeMaxDynamicSharedMemorySize,
                         SMEM_MMA);
    cudaFuncSetAttribute(head_mma, cudaFuncAttributeMaxDynamicSharedMemorySize,
                         SMEM_HEAD);

    repack_w1<<<(NBLK * 5 * 240 * 64 + 255) / 256, 256>>>(dil_w, cond_w);
    repack_w2<<<(NBLK * 2 * (240 + 120) * 64 + 255) / 256, 256>>>(skip_w, res_w);
    repack_whead<<<(2 * 4 * 256 * 64 + 255) / 256, 256>>>(out_w, end_w);
    prologue_res<<<(BB * TLEN * 16 + 255) / 256, 256>>>(wav, wav_w, wav_b);
    prologue_cond<<<(BB * TLEN * 16 + 255) / 256, 256>>>(cond);

    dim3 gridB(TLEN / 128, BB);
    for (int i = 0; i < NBLK; i++) {
        int d = 1 << (i % 8);
        block_mma<<<gridB, 256, SMEM_MMA>>>(dil_b, cond_b, skip_b, res_b,
                                            i, d, (i == 0) ? 1 : 0, i & 1);
    }
    head_mma<<<gridB, 256, SMEM_HEAD>>>(out_b, end_b, (float*)d_out);
}

// round 16
// speedup vs baseline: 2.8615x; 1.3511x over previous
#include <cuda_runtime.h>
#include <cuda_fp16.h>
#include <math.h>
#include <stdint.h>

#define BB   4
#define TLEN 32768
#define NM   80
#define RC   120
#define SC   240
#define NBLK 16
#define NC   256

// ---------------- device scratch (no allocations allowed) ----------------
__device__ uint4 g_resAH[BB * TLEN * 16];
__device__ uint4 g_resAL[BB * TLEN * 16];
__device__ uint4 g_resBH[BB * TLEN * 16];
__device__ uint4 g_resBL[BB * TLEN * 16];
__device__ uint4 g_condH[BB * TLEN * 16];   // cond: single fp16
__device__ float g_skip [BB * TLEN * SC];   // [b][t][c]
__device__ uint4 g_W1h[NBLK * 5 * 1920];    // phase1 fp16, K packed 320
__device__ uint4 g_W2sh[NBLK * 2 * 1920];   // skip [240][64] fp16
__device__ uint4 g_W2rh[NBLK * 2 * 960];    // res  [120][64] fp16
__device__ uint4 g_Woh[4 * 2048];           // out_w [256][64] chunks fp16
__device__ uint4 g_Weh[4 * 2048];           // end_w [256][64] chunks fp16

// ---------------- helpers -------------------------------------------------
__device__ __forceinline__ uint32_t smem_u32(const void* p) {
    uint32_t a;
    asm("{ .reg .u64 t; cvta.to.shared.u64 t, %1; cvt.u32.u64 %0, t; }"
        : "=r"(a) : "l"(p));
    return a;
}
__device__ __forceinline__ uint32_t sw128(uint32_t b) { return b ^ ((b >> 3) & 0x70); }

union U4H { uint4 u; __half h[8]; };
union U1H { uint32_t u; __half h[2]; };

__device__ __forceinline__ void split_fp16(float x, __half& hi, __half& lo) {
    hi = __float2half(x);
    lo = __float2half(x - __half2float(hi));
}
__device__ __forceinline__ float fast_tanh(float x) {
    return 1.f - 2.f / (1.f + __expf(2.f * x));
}
__device__ __forceinline__ float fast_sigmoid(float x) {
    return 1.f / (1.f + __expf(-x));
}

__device__ __forceinline__ void ldsm_x4(uint32_t* r, uint32_t addr) {
    asm volatile("ldmatrix.sync.aligned.m8n8.x4.shared.b16 {%0,%1,%2,%3}, [%4];"
                 : "=r"(r[0]), "=r"(r[1]), "=r"(r[2]), "=r"(r[3]) : "r"(addr));
}
__device__ __forceinline__ void ldsm_x2(uint32_t* r, uint32_t addr) {
    asm volatile("ldmatrix.sync.aligned.m8n8.x2.shared.b16 {%0,%1}, [%2];"
                 : "=r"(r[0]), "=r"(r[1]) : "r"(addr));
}
__device__ __forceinline__ void mma16816(float* c, const uint32_t* a,
                                         uint32_t b0, uint32_t b1) {
    asm("mma.sync.aligned.m16n8k16.row.col.f32.f16.f16.f32 "
        "{%0,%1,%2,%3}, {%4,%5,%6,%7}, {%8,%9}, {%0,%1,%2,%3};"
        : "+f"(c[0]), "+f"(c[1]), "+f"(c[2]), "+f"(c[3])
        : "r"(a[0]), "r"(a[1]), "r"(a[2]), "r"(a[3]), "r"(b0), "r"(b1));
}
__device__ __forceinline__ void cpa16(uint32_t smem, const void* gmem, uint32_t ssz) {
    asm volatile("cp.async.cg.shared.global [%0], [%1], 16, %2;"
                 :: "r"(smem), "l"(gmem), "r"(ssz) : "memory");
}
#define CPA_COMMIT() asm volatile("cp.async.commit_group;" ::: "memory")
template <int N> __device__ __forceinline__ void cpa_wait() {
    asm volatile("cp.async.wait_group %0;" :: "n"(N) : "memory");
}

// ---------------- merged weight repack kernel -----------------------------
// ranges: [0, T1): W1 | [T1, T1+TS): W2 skip | +TR: W2 res | then head Wo/We
#define T1   (NBLK * 5 * 240 * 64)
#define TS   (NBLK * 2 * 240 * 64)
#define TR   (NBLK * 2 * 120 * 64)
#define TH   (4 * 256 * 64)
__global__ void repack_all(const float* __restrict__ dil_w,
                           const float* __restrict__ cond_w,
                           const float* __restrict__ skip_w,
                           const float* __restrict__ res_w,
                           const float* __restrict__ out_w,
                           const float* __restrict__ end_w) {
    int idx = blockIdx.x * blockDim.x + threadIdx.x;
    if (idx < T1) {
        int kk = idx & 63;
        int n  = (idx >> 6) % 240;
        int q  = (idx / (64 * 240)) % 5;
        int i  = idx / (64 * 240 * 5);
        int c  = (n >> 1) + (n & 1) * 120;
        int kpos = q * 64 + kk;
        float w;
        if (kpos < 120)      w = dil_w[((i*240 + c)*120 + kpos)*2 + 0];
        else if (kpos < 240) w = dil_w[((i*240 + c)*120 + (kpos - 120))*2 + 1];
        else                 w = cond_w[(i*240 + c)*80 + (kpos - 240)];
        int elem = sw128(n * 128 + kk * 2) >> 1;
        ((__half*)g_W1h)[(size_t)(i * 5 + q) * 15360 + elem] = __float2half(w);
    } else if (idx < T1 + TS) {
        int j = idx - T1;
        int kk = j & 63;
        int c  = (j >> 6) % 240;
        int q  = (j / (64 * 240)) % 2;
        int i  = j / (64 * 240 * 2);
        int k  = q * 64 + kk;
        float w = (k < 120) ? skip_w[(i*240 + c)*120 + k] : 0.f;
        int elem = sw128(c * 128 + kk * 2) >> 1;
        ((__half*)g_W2sh)[(size_t)(i * 2 + q) * 15360 + elem] = __float2half(w);
    } else if (idx < T1 + TS + TR) {
        int j = idx - T1 - TS;
        int kk = j & 63;
        int c  = (j >> 6) % 120;
        int q  = (j / (64 * 120)) % 2;
        int i  = j / (64 * 120 * 2);
        int k  = q * 64 + kk;
        float w = (k < 120) ? res_w[(i*120 + c)*120 + k] : 0.f;
        int elem = sw128(c * 128 + kk * 2) >> 1;
        ((__half*)g_W2rh)[(size_t)(i * 2 + q) * 7680 + elem] = __float2half(w);
    } else if (idx < T1 + TS + TR + 2 * TH) {
        int j = idx - T1 - TS - TR;
        int sel = j / TH;
        j %= TH;
        int kk = j & 63;
        int n  = (j >> 6) % 256;
        int q  = j / (64 * 256);
        int k  = q * 64 + kk;
        float w;
        if (sel == 0) w = (k < 240) ? out_w[n * 240 + k] : 0.f;
        else          w = end_w[n * 256 + k];
        int elem = sw128(n * 128 + kk * 2) >> 1;
        size_t base = (size_t)q * 16384;
        if (sel == 0) ((__half*)g_Woh)[base + elem] = __float2half(w);
        else          ((__half*)g_Weh)[base + elem] = __float2half(w);
    }
}

// ---------------- merged prologue (res + cond) ----------------------------
__global__ void prologue_all(const float* __restrict__ wav,
                             const float* __restrict__ wav_w,
                             const float* __restrict__ wav_b,
                             const float* __restrict__ cond) {
    int idx = blockIdx.x * blockDim.x + threadIdx.x;
    const int total = BB * TLEN * 16;
    if (idx >= total) return;
    int chunk = idx & 15;
    int t = (idx >> 4) % TLEN;
    int b = idx / (TLEN * 16);
    float wv = wav[(size_t)b * TLEN + t];
    U4H uh, ul, uc;
    #pragma unroll
    for (int e = 0; e < 8; e++) {
        int c = chunk * 8 + e;
        float v = (c < RC) ? (wav_w[c] * wv + wav_b[c]) : 0.f;
        split_fp16(v, uh.h[e], ul.h[e]);
        float cv = (c < NM) ? cond[((size_t)b * NM + c) * TLEN + t] : 0.f;
        uc.h[e] = __float2half(cv);
    }
    g_resAH[idx] = uh.u;
    g_resAL[idx] = ul.u;
    g_condH[idx] = uc.u;
}

// ---------------- mma per-layer kernel (512 thr, fp16, cp.async) ----------
#define OFF_BA   0
#define OFF_BB   1024
#define OFF_X    4096
#define XBUF(i)  (OFF_X + (i) * 16384)          // [128][64] fp16 = 16KB
#define OFF_W    36864
#define WBUF(i)  (OFF_W + (i) * 30720)          // [240][64] fp16
#define SMEM_MMA 98304

__global__ void __launch_bounds__(512, 1) block_mma(
    const float* __restrict__ dil_b, const float* __restrict__ cond_b,
    const float* __restrict__ skip_b, const float* __restrict__ res_b,
    int layer, int d, int first, int swap)
{
    extern __shared__ __align__(16) char sm[];
    const uint32_t smb = smem_u32(sm);
    const int tid  = threadIdx.x;
    const int lane = tid & 31;
    const int wid  = tid >> 5;
    const int mw   = wid >> 1;            // 0..7 (m, 16 rows each)
    const int nw   = wid & 1;             // 0..1 (n)
    const int b    = blockIdx.y;
    const int t0   = blockIdx.x * 128;

    const uint4* resInH = swap ? g_resBH : g_resAH;
    const uint4* resInL = swap ? g_resBL : g_resAL;
    uint4* resOutH = swap ? g_resAH : g_resBH;
    uint4* resOutL = swap ? g_resAL : g_resBL;

    // ---- staging helpers ----
    auto stage1 = [&](int q) {
        uint32_t xb = smb + XBUF(q & 1);
        for (int e = tid; e < 1024; e += 512) {
            int r = e >> 3, ii = e & 7;
            int kg = q * 8 + ii;
            const uint4* sH; int t; int grp;
            if (kg < 15)      { sH = resInH;  t = t0 - d + r; grp = kg; }
            else if (kg < 30) { sH = resInH;  t = t0 + r;     grp = kg - 15; }
            else              { sH = g_condH; t = t0 + r;     grp = kg - 30; }
            uint32_t ok = (t >= 0) ? 16u : 0u;
            int tc = (t >= 0) ? t : 0;
            size_t si = ((size_t)b * TLEN + tc) * 16 + grp;
            uint32_t byte = sw128((r << 7) + (ii << 4));
            cpa16(xb + byte, sH + si, ok);
        }
        uint32_t wb = smb + WBUF(q & 1);
        size_t wgb = (size_t)(layer * 5 + q) * 1920;
        for (int e = tid; e < 1920; e += 512)
            cpa16(wb + e * 16, g_W1h + wgb + e, 16);
        CPA_COMMIT();
    };
    auto stage2s = [&](int chunk, int buf) {
        uint32_t wb = smb + WBUF(buf);
        size_t bs = (size_t)(layer * 2 + chunk) * 1920;
        for (int e = tid; e < 1920; e += 512)
            cpa16(wb + e * 16, g_W2sh + bs + e, 16);
        CPA_COMMIT();
    };
    auto stage2r = [&](int chunk, int buf) {
        uint32_t wb = smb + WBUF(buf);
        size_t br = (size_t)(layer * 2 + chunk) * 960;
        for (int e = tid; e < 960; e += 512)
            cpa16(wb + e * 16, g_W2rh + br + e, 16);
        CPA_COMMIT();
    };

    stage1(0);

    float* biasA = (float*)(sm + OFF_BA);
    float* biasB = (float*)(sm + OFF_BB);
    for (int e = tid; e < 240; e += 512)
        biasA[e] = dil_b[layer * 240 + e] + cond_b[layer * 240 + e];
    for (int e = tid; e < 360; e += 512)
        biasB[e] = (e < 240) ? skip_b[layer * 240 + e] : res_b[layer * 120 + e - 240];

    // ========== phase 1: g[128t x 240n(permuted)], K=320 ==========
    float ac[15][4];
    #pragma unroll
    for (int nt = 0; nt < 15; nt++)
        #pragma unroll
        for (int e = 0; e < 4; e++) ac[nt][e] = 0.f;

    const int bn   = nw * 120 + (lane & 7);
    const int bhi  = (lane >> 4) << 3;
    const int bsel = (lane >> 3) & 1;

    for (int q = 0; q < 5; q++) {
        if (q < 4) stage1(q + 1);
        else       stage2s(0, 1);
        cpa_wait<1>();
        __syncthreads();
        uint32_t xb  = smb + XBUF(q & 1);
        uint32_t wbh = smb + WBUF(q & 1);
        #pragma unroll
        for (int kt = 0; kt < 4; kt++) {
            uint32_t ah[4];
            {
                int ar = mw * 16 + (lane & 15);
                int ack = kt * 2 + (lane >> 4);
                uint32_t ab = ar * 128 + (((uint32_t)(ack ^ (ar & 7))) << 4);
                ldsm_x4(ah, xb + ab);
            }
            int bck = kt * 2 + bsel;
            #pragma unroll
            for (int j = 0; j < 7; j++) {
                int n0 = bn + j * 16 + bhi;
                uint32_t bb = n0 * 128 + (((uint32_t)(bck ^ (n0 & 7))) << 4);
                uint32_t bq[4];
                ldsm_x4(bq, wbh + bb);
                mma16816(ac[2*j],   ah, bq[0], bq[1]);
                mma16816(ac[2*j+1], ah, bq[2], bq[3]);
            }
            {   // nt = 14
                int n = nw * 120 + 112 + (lane & 7);
                uint32_t bb = n * 128 + (((uint32_t)(bck ^ (n & 7))) << 4);
                uint32_t bh2[2];
                ldsm_x2(bh2, wbh + bb);
                mma16816(ac[14], ah, bh2[0], bh2[1]);
            }
        }
        __syncthreads();
    }

    // ========== gating (registers) -> A2 tile (fp16) in X buffers ==========
    #pragma unroll
    for (int nt = 0; nt < 15; nt++) {
        int p = nw * 60 + nt * 4 + (lane & 3);
        int reg = (p < 64) ? 0 : 1;
        int p2 = p & 63;
        float ba_t = biasA[p];
        float ba_s = biasA[p + 120];
        #pragma unroll
        for (int rh = 0; rh < 2; rh++) {
            int r = mw * 16 + (lane >> 2) + rh * 8;
            float gt = ac[nt][rh * 2 + 0] + ba_t;
            float gs = ac[nt][rh * 2 + 1] + ba_s;
            float v = fast_tanh(gt) * fast_sigmoid(gs);
            uint32_t byte = r * 128 + (((uint32_t)((p2 >> 3) ^ (r & 7))) << 4)
                          + (p2 & 7) * 2;
            *(__half*)(sm + XBUF(reg) + byte) = __float2half(v);
        }
    }
    // zero-pad A2 chunk1 (p 120..127)
    if (tid < 128) {
        uint32_t byte = tid * 128 + ((7u ^ (tid & 7)) << 4);
        *(uint4*)(sm + XBUF(1) + byte) = make_uint4(0, 0, 0, 0);
    }

    // ========== phase 2a: skip[128t x 240c], K=120 ==========
    float sk[15][4];
    #pragma unroll
    for (int nt = 0; nt < 15; nt++)
        #pragma unroll
        for (int e = 0; e < 4; e++) sk[nt][e] = 0.f;

    for (int q2 = 0; q2 < 2; q2++) {
        if (q2 == 0) stage2s(1, 0);
        else         stage2r(0, 1);
        cpa_wait<1>();
        __syncthreads();
        uint32_t xb  = smb + XBUF(q2);
        uint32_t wbh = smb + WBUF(1 - q2);
        #pragma unroll
        for (int kt = 0; kt < 4; kt++) {
            uint32_t ah[4];
            {
                int ar = mw * 16 + (lane & 15);
                int ack = kt * 2 + (lane >> 4);
                uint32_t ab = ar * 128 + (((uint32_t)(ack ^ (ar & 7))) << 4);
                ldsm_x4(ah, xb + ab);
            }
            int bck = kt * 2 + bsel;
            #pragma unroll
            for (int j = 0; j < 7; j++) {
                int n0 = bn + j * 16 + bhi;
                uint32_t bb = n0 * 128 + (((uint32_t)(bck ^ (n0 & 7))) << 4);
                uint32_t bq[4];
                ldsm_x4(bq, wbh + bb);
                mma16816(sk[2*j],   ah, bq[0], bq[1]);
                mma16816(sk[2*j+1], ah, bq[2], bq[3]);
            }
            {
                int n = nw * 120 + 112 + (lane & 7);
                uint32_t bb = n * 128 + (((uint32_t)(bck ^ (n & 7))) << 4);
                uint32_t bh2[2];
                ldsm_x2(bh2, wbh + bb);
                mma16816(sk[14], ah, bh2[0], bh2[1]);
            }
        }
        __syncthreads();
    }

    // skip epilogue: [b][t][240] fp32 accumulate
    #pragma unroll
    for (int nt = 0; nt < 15; nt++) {
        int c = nw * 120 + nt * 8 + 2 * (lane & 3);
        float b0 = biasB[c], b1 = biasB[c + 1];
        #pragma unroll
        for (int rh = 0; rh < 2; rh++) {
            int t = t0 + mw * 16 + (lane >> 2) + rh * 8;
            size_t gi = ((size_t)b * TLEN + t) * 240 + c;
            float2 v;
            v.x = sk[nt][rh * 2 + 0] + b0;
            v.y = sk[nt][rh * 2 + 1] + b1;
            if (!first) {
                float2 o = *(float2*)(g_skip + gi);
                v.x += o.x; v.y += o.y;
            }
            *(float2*)(g_skip + gi) = v;
        }
    }

    // ========== phase 2b: res[128t x 120c], K=120 ==========
    {
        float rs[8][4];
        #pragma unroll
        for (int nt = 0; nt < 8; nt++)
            #pragma unroll
            for (int e = 0; e < 4; e++) rs[nt][e] = 0.f;
        const int NT = 8 - nw;

        for (int q2 = 0; q2 < 2; q2++) {
            if (q2 == 0) { stage2r(1, 0); cpa_wait<1>(); }
            else         { cpa_wait<0>(); }
            __syncthreads();
            uint32_t xb  = smb + XBUF(q2);
            uint32_t wbh = smb + WBUF(1 - q2);
            #pragma unroll
            for (int kt = 0; kt < 4; kt++) {
                uint32_t ah[4];
                {
                    int ar = mw * 16 + (lane & 15);
                    int ack = kt * 2 + (lane >> 4);
                    uint32_t ab = ar * 128 + (((uint32_t)(ack ^ (ar & 7))) << 4);
                    ldsm_x4(ah, xb + ab);
                }
                int bn2 = nw * 64 + (lane & 7);
                int bck = kt * 2 + bsel;
                #pragma unroll
                for (int nt = 0; nt < 8; nt++) {
                    if (nt < NT) {
                        int n = bn2 + nt * 8;
                        uint32_t bb = n * 128 + (((uint32_t)(bck ^ (n & 7))) << 4);
                        uint32_t bh2[2];
                        ldsm_x2(bh2, wbh + bb);
                        mma16816(rs[nt], ah, bh2[0], bh2[1]);
                    }
                }
            }
            __syncthreads();
        }

        // res epilogue: resOut = rs + bias + resIn(hi+lo); store fp16 hi/lo
        const uint32_t* rInH = (const uint32_t*)resInH;
        const uint32_t* rInL = (const uint32_t*)resInL;
        uint32_t* rOutH = (uint32_t*)resOutH;
        uint32_t* rOutL = (uint32_t*)resOutL;
        #pragma unroll
        for (int nt = 0; nt < 8; nt++) {
            if (nt < NT) {
                int c = nw * 64 + nt * 8 + 2 * (lane & 3);
                float b0 = biasB[240 + c], b1 = biasB[240 + c + 1];
                #pragma unroll
                for (int rh = 0; rh < 2; rh++) {
                    int t = t0 + mw * 16 + (lane >> 2) + rh * 8;
                    size_t ri = ((size_t)b * TLEN + t) * 64 + (c >> 1);
                    U1H vh, vl, oh, ol;
                    vh.u = rInH[ri]; vl.u = rInL[ri];
                    float o0 = rs[nt][rh * 2 + 0] + b0
                             + __half2float(vh.h[0]) + __half2float(vl.h[0]);
                    float o1 = rs[nt][rh * 2 + 1] + b1
                             + __half2float(vh.h[1]) + __half2float(vl.h[1]);
                    split_fp16(o0, oh.h[0], ol.h[0]);
                    split_fp16(o1, oh.h[1], ol.h[1]);
                    rOutH[ri] = oh.u;
                    rOutL[ri] = ol.u;
                }
            }
        }
    }
    // zero pad channels 120-127 of resOut
    if (tid < 128) {
        size_t rp = ((size_t)b * TLEN + t0 + tid) * 16 + 15;
        resOutH[rp] = make_uint4(0, 0, 0, 0);
        resOutL[rp] = make_uint4(0, 0, 0, 0);
    }
}

// ---------------- fused mma head kernel (fp16, 256 thr — proven R12) ------
#define HOFF_OB   0
#define HOFF_EB   1024
#define HOFF_A1   2048
#define HOFF_WH   18432
#define HOFF_A2   51200
#define SMEM_HEAD 116736

__global__ void __launch_bounds__(256, 1) head_mma(
    const float* __restrict__ out_b, const float* __restrict__ end_b,
    float* __restrict__ out)
{
    extern __shared__ __align__(16) char sm[];
    const uint32_t smb = smem_u32(sm);
    const int tid  = threadIdx.x;
    const int lane = tid & 31;
    const int wid  = tid >> 5;
    const int mw   = wid >> 1;
    const int nw   = wid & 1;
    const int b    = blockIdx.y;
    const int t0   = blockIdx.x * 128;

    float* obs = (float*)(sm + HOFF_OB);
    float* ebs = (float*)(sm + HOFF_EB);
    for (int e = tid; e < 256; e += 256) { obs[e] = out_b[e]; ebs[e] = end_b[e]; }

    float ac[2][16][4];
    #pragma unroll
    for (int mt = 0; mt < 2; mt++)
        #pragma unroll
        for (int nt = 0; nt < 16; nt++)
            #pragma unroll
            for (int e = 0; e < 4; e++) ac[mt][nt][e] = 0.f;

    for (int q = 0; q < 4; q++) {
        __syncthreads();
        for (int e = tid; e < 1024; e += 256) {
            int r = e >> 3, ii = e & 7;
            int c0 = q * 64 + ii * 8;
            U4H uh;
            if (c0 < 240) {
                size_t gi = ((size_t)b * TLEN + t0 + r) * 240 + c0;
                float4 v0 = *(const float4*)(g_skip + gi);
                float4 v1 = *(const float4*)(g_skip + gi + 4);
                float vv[8] = {v0.x, v0.y, v0.z, v0.w, v1.x, v1.y, v1.z, v1.w};
                #pragma unroll
                for (int k = 0; k < 8; k++)
                    uh.h[k] = __float2half(fmaxf(vv[k], 0.f));
            } else {
                uh.u = make_uint4(0,0,0,0);
            }
            uint32_t byte = sw128((r << 7) + (ii << 4));
            *(uint4*)(sm + HOFF_A1 + byte) = uh.u;
        }
        for (int e = tid; e < 2048; e += 256)
            ((uint4*)(sm + HOFF_WH))[e] = g_Woh[q * 2048 + e];
        __syncthreads();
        #pragma unroll
        for (int kt = 0; kt < 4; kt++) {
            uint32_t ah[2][4];
            #pragma unroll
            for (int mt = 0; mt < 2; mt++) {
                int ar = mw * 32 + mt * 16 + (lane & 15);
                int ack = kt * 2 + (lane >> 4);
                uint32_t ab = ar * 128 + (((uint32_t)(ack ^ (ar & 7))) << 4);
                ldsm_x4(ah[mt], smb + HOFF_A1 + ab);
            }
            int bn = nw * 128 + (lane & 7);
            int bhi2 = (lane >> 4) << 3;
            int bsel = (lane >> 3) & 1;
            int bck = kt * 2 + bsel;
            #pragma unroll
            for (int j = 0; j < 8; j++) {
                int n0 = bn + j * 16 + bhi2;
                uint32_t bb = n0 * 128 + (((uint32_t)(bck ^ (n0 & 7))) << 4);
                uint32_t bq[4];
                ldsm_x4(bq, smb + HOFF_WH + bb);
                #pragma unroll
                for (int mt = 0; mt < 2; mt++) {
                    mma16816(ac[mt][2*j],   ah[mt], bq[0], bq[1]);
                    mma16816(ac[mt][2*j+1], ah[mt], bq[2], bq[3]);
                }
            }
        }
    }

    __syncthreads();
    #pragma unroll
    for (int nt = 0; nt < 16; nt++) {
        int p = nw * 128 + nt * 8 + 2 * (lane & 3);
        int chunk = p >> 6;
        int p2 = p & 63;
        float b0 = obs[p], b1 = obs[p + 1];
        #pragma unroll
        for (int mt = 0; mt < 2; mt++) {
            #pragma unroll
            for (int rh = 0; rh < 2; rh++) {
                int r = mw * 32 + mt * 16 + (lane >> 2) + rh * 8;
                float v0 = fmaxf(ac[mt][nt][rh * 2 + 0] + b0, 0.f);
                float v1 = fmaxf(ac[mt][nt][rh * 2 + 1] + b1, 0.f);
                U1H ph;
                ph.h[0] = __float2half(v0);
                ph.h[1] = __float2half(v1);
                uint32_t byte = r * 128 + (((uint32_t)((p2 >> 3) ^ (r & 7))) << 4)
                              + (p2 & 7) * 2;
                *(uint32_t*)(sm + HOFF_A2 + chunk * 16384 + byte) = ph.u;
            }
        }
    }

    #pragma unroll
    for (int mt = 0; mt < 2; mt++)
        #pragma unroll
        for (int nt = 0; nt < 16; nt++)
            #pragma unroll
            for (int e = 0; e < 4; e++) ac[mt][nt][e] = 0.f;

    for (int q = 0; q < 4; q++) {
        __syncthreads();
        for (int e = tid; e < 2048; e += 256)
            ((uint4*)(sm + HOFF_WH))[e] = g_Weh[q * 2048 + e];
        __syncthreads();
        #pragma unroll
        for (int kt = 0; kt < 4; kt++) {
            uint32_t ah[2][4];
            #pragma unroll
            for (int mt = 0; mt < 2; mt++) {
                int ar = mw * 32 + mt * 16 + (lane & 15);
                int ack = kt * 2 + (lane >> 4);
                uint32_t ab = ar * 128 + (((uint32_t)(ack ^ (ar & 7))) << 4);
                ldsm_x4(ah[mt], smb + HOFF_A2 + q * 16384 + ab);
            }
            int bn = nw * 128 + (lane & 7);
            int bhi2 = (lane >> 4) << 3;
            int bsel = (lane >> 3) & 1;
            int bck = kt * 2 + bsel;
            #pragma unroll
            for (int j = 0; j < 8; j++) {
                int n0 = bn + j * 16 + bhi2;
                uint32_t bb = n0 * 128 + (((uint32_t)(bck ^ (n0 & 7))) << 4);
                uint32_t bq[4];
                ldsm_x4(bq, smb + HOFF_WH + bb);
                #pragma unroll
                for (int mt = 0; mt < 2; mt++) {
                    mma16816(ac[mt][2*j],   ah[mt], bq[0], bq[1]);
                    mma16816(ac[mt][2*j+1], ah[mt], bq[2], bq[3]);
                }
            }
        }
    }

    #pragma unroll
    for (int nt = 0; nt < 16; nt++) {
        int o0 = nw * 128 + nt * 8 + 2 * (lane & 3);
        float b0 = ebs[o0], b1 = ebs[o0 + 1];
        #pragma unroll
        for (int mt = 0; mt < 2; mt++) {
            #pragma unroll
            for (int rh = 0; rh < 2; rh++) {
                int t = t0 + mw * 32 + mt * 16 + (lane >> 2) + rh * 8;
                out[((size_t)b * NC + o0) * TLEN + t]     = ac[mt][nt][rh * 2 + 0] + b0;
                out[((size_t)b * NC + o0 + 1) * TLEN + t] = ac[mt][nt][rh * 2 + 1] + b1;
            }
        }
    }
}

// ---------------- host launcher -------------------------------------------
extern "C" void kernel_launch(void* const* d_in, const int* in_sizes, int n_in,
                              void* d_out, int out_size) {
    const float* wav    = (const float*)d_in[0];
    const float* cond   = (const float*)d_in[1];
    const float* wav_w  = (const float*)d_in[2];
    const float* wav_b  = (const float*)d_in[3];
    const float* cond_w = (const float*)d_in[4];
    const float* cond_b = (const float*)d_in[5];
    const float* dil_w  = (const float*)d_in[6];
    const float* dil_b  = (const float*)d_in[7];
    const float* skip_w = (const float*)d_in[8];
    const float* skip_b = (const float*)d_in[9];
    const float* res_w  = (const float*)d_in[10];
    const float* res_b  = (const float*)d_in[11];
    const float* out_w  = (const float*)d_in[12];
    const float* out_b  = (const float*)d_in[13];
    const float* end_w  = (const float*)d_in[14];
    const float* end_b  = (const float*)d_in[15];

    cudaFuncSetAttribute(block_mma, cudaFuncAttributeMaxDynamicSharedMemorySize,
                         SMEM_MMA);
    cudaFuncSetAttribute(head_mma, cudaFuncAttributeMaxDynamicSharedMemorySize,
                         SMEM_HEAD);

    const int totalRW = T1 + TS + TR + 2 * TH;
    repack_all<<<(totalRW + 255) / 256, 256>>>(dil_w, cond_w, skip_w, res_w,
                                               out_w, end_w);
    prologue_all<<<(BB * TLEN * 16 + 255) / 256, 256>>>(wav, wav_w, wav_b, cond);

    dim3 gridB(TLEN / 128, BB);
    for (int i = 0; i < NBLK; i++) {
        int d = 1 << (i % 8);
        block_mma<<<gridB, 512, SMEM_MMA>>>(dil_b, cond_b, skip_b, res_b,
                                            i, d, (i == 0) ? 1 : 0, i & 1);
    }
    head_mma<<<gridB, 256, SMEM_HEAD>>>(out_b, end_b, (float*)d_out);
}